// round 2
// baseline (speedup 1.0000x reference)
#include <cuda_runtime.h>
#include <math.h>

// ---------------- problem constants ----------------
constexpr int Bn   = 32;
constexpr int Hh   = 56;
constexpr int Wd   = 56;
constexpr int Cc   = 384;
constexpr int NHd  = 12;
constexpr int WS   = 7;
constexpr int SS   = 3;
constexpr int Ntok = WS * WS;            // 49
constexpr int NWim = (Hh/WS) * (Wd/WS);  // 64
constexpr int HD   = Cc / NHd;           // 32
constexpr int MLPH = 4 * Cc;             // 1536
constexpr int Mrows = Bn * Hh * Wd;      // 100352 tokens
constexpr int ThreeC = 3 * Cc;           // 1152

// ---------------- scratch (device globals; no allocs allowed) ----------------
__device__ float g_xw [(size_t)Mrows * Cc];     // LN1 + shift + window-partitioned; later reused as proj output
__device__ float g_qkv[(size_t)Mrows * ThreeC]; // qkv GEMM output
__device__ float g_att[(size_t)Mrows * Cc];     // attention output (pre-proj)
__device__ float g_x2 [(size_t)Mrows * Cc];     // residual after attention
__device__ float g_h  [(size_t)Mrows * Cc];     // LN2 output
__device__ float g_f1 [(size_t)Mrows * MLPH];   // fc1+gelu output

// ---------------- block reduce (sum, sumsq) over 128 threads ----------------
__device__ __forceinline__ void blockReduce2(float& s, float& s2) {
    #pragma unroll
    for (int o = 16; o > 0; o >>= 1) {
        s  += __shfl_down_sync(0xFFFFFFFFu, s,  o);
        s2 += __shfl_down_sync(0xFFFFFFFFu, s2, o);
    }
    __shared__ float sh[4][2];
    int w = threadIdx.x >> 5, l = threadIdx.x & 31;
    if (l == 0) { sh[w][0] = s; sh[w][1] = s2; }
    __syncthreads();
    if (threadIdx.x == 0) {
        float a = 0.f, b = 0.f;
        #pragma unroll
        for (int i = 0; i < 4; i++) { a += sh[i][0]; b += sh[i][1]; }
        sh[0][0] = a; sh[0][1] = b;
    }
    __syncthreads();
    s = sh[0][0]; s2 = sh[0][1];
}

// ---------------- kernel 1: LN1 + cyclic shift + window partition ----------------
// out token t = widx*49 + n  maps to shifted-image coords, gathered from x.
__global__ void k_ln1(const float* __restrict__ x, const float* __restrict__ w,
                      const float* __restrict__ bi, float* __restrict__ out) {
    int t = blockIdx.x;
    int widx = t / Ntok, n = t % Ntok;
    int b  = widx / NWim, wi = widx % NWim;
    int wh = wi / 8, ww = wi % 8;
    int r  = wh * WS + n / WS, c = ww * WS + n % WS;
    int sh = (r + SS) % Hh, sw = (c + SS) % Wd;
    const float* src = x + ((size_t)b * (Hh*Wd) + sh * Wd + sw) * Cc;

    int tid = threadIdx.x;
    float vals[3]; float s = 0.f, s2 = 0.f;
    #pragma unroll
    for (int i = 0; i < 3; i++) {
        float v = src[tid + i * 128];
        vals[i] = v; s += v; s2 += v * v;
    }
    blockReduce2(s, s2);
    float mean = s * (1.f / Cc);
    float var  = s2 * (1.f / Cc) - mean * mean;
    float inv  = rsqrtf(var + 1e-5f);
    float* dst = out + (size_t)t * Cc;
    #pragma unroll
    for (int i = 0; i < 3; i++) {
        int cI = tid + i * 128;
        dst[cI] = (vals[i] - mean) * inv * w[cI] + bi[cI];
    }
}

// ---------------- kernel: plain LN (for LN2) ----------------
__global__ void k_ln2(const float* __restrict__ x, const float* __restrict__ w,
                      const float* __restrict__ bi, float* __restrict__ out) {
    int t = blockIdx.x;
    const float* src = x + (size_t)t * Cc;
    int tid = threadIdx.x;
    float vals[3]; float s = 0.f, s2 = 0.f;
    #pragma unroll
    for (int i = 0; i < 3; i++) {
        float v = src[tid + i * 128];
        vals[i] = v; s += v; s2 += v * v;
    }
    blockReduce2(s, s2);
    float mean = s * (1.f / Cc);
    float var  = s2 * (1.f / Cc) - mean * mean;
    float inv  = rsqrtf(var + 1e-5f);
    float* dst = out + (size_t)t * Cc;
    #pragma unroll
    for (int i = 0; i < 3; i++) {
        int cI = tid + i * 128;
        dst[cI] = (vals[i] - mean) * inv * w[cI] + bi[cI];
    }
}

// ---------------- generic 64x64 tiled SGEMM: C = A @ W (+bias, +gelu/residual) ----------------
// EPI: 0 = +bias ; 1 = +bias then exact GELU ; 2 = +bias then +res
template <int EPI>
__global__ void k_gemm(const float* __restrict__ A, const float* __restrict__ Bm,
                       const float* __restrict__ bias, const float* __restrict__ res,
                       float* __restrict__ Cm, int M, int Ncols, int K) {
    __shared__ float As[16][68];
    __shared__ float Bs[16][68];
    int tid  = threadIdx.x;
    int row0 = blockIdx.y * 64, col0 = blockIdx.x * 64;
    int ty = tid / 16, tx = tid % 16;
    float acc[4][4] = {};

    for (int kt = 0; kt < K; kt += 16) {
        {   // A tile: 64 rows x 16 k
            int r = tid >> 2, kq = (tid & 3) * 4;
            float4 a = *(const float4*)&A[(size_t)(row0 + r) * K + kt + kq];
            As[kq + 0][r] = a.x; As[kq + 1][r] = a.y;
            As[kq + 2][r] = a.z; As[kq + 3][r] = a.w;
        }
        {   // B tile: 16 k x 64 cols
            int r = tid >> 4, cq = (tid & 15) * 4;
            *(float4*)&Bs[r][cq] = *(const float4*)&Bm[(size_t)(kt + r) * Ncols + col0 + cq];
        }
        __syncthreads();
        #pragma unroll
        for (int k = 0; k < 16; k++) {
            float a[4], b[4];
            #pragma unroll
            for (int i = 0; i < 4; i++) a[i] = As[k][ty * 4 + i];
            #pragma unroll
            for (int j = 0; j < 4; j++) b[j] = Bs[k][tx * 4 + j];
            #pragma unroll
            for (int i = 0; i < 4; i++)
                #pragma unroll
                for (int j = 0; j < 4; j++)
                    acc[i][j] = fmaf(a[i], b[j], acc[i][j]);
        }
        __syncthreads();
    }
    #pragma unroll
    for (int i = 0; i < 4; i++) {
        int r = row0 + ty * 4 + i;
        #pragma unroll
        for (int j = 0; j < 4; j++) {
            int c = col0 + tx * 4 + j;
            float v = acc[i][j] + bias[c];
            if (EPI == 1) v = 0.5f * v * (1.f + erff(v * 0.70710678118654752f));
            if (EPI == 2) v += res[(size_t)r * Ncols + c];
            Cm[(size_t)r * Ncols + c] = v;
        }
    }
}

// ---------------- attention: one block per (window, head) ----------------
__global__ void k_attn(const float* __restrict__ qkv, const float* __restrict__ rpb,
                       float* __restrict__ out) {
    int blk  = blockIdx.x;
    int widx = blk / NHd, hh = blk % NHd;
    int wi = widx % NWim;
    int wh = wi / 8, ww = wi % 8;

    __shared__ float sq[Ntok * HD], sk[Ntok * HD], sv[Ntok * HD];
    __shared__ float sc[Ntok * Ntok];
    __shared__ int   reg[Ntok];

    int tid = threadIdx.x;
    for (int idx = tid; idx < Ntok * HD; idx += 128) {
        int tok = widx * Ntok + idx / HD;
        int d   = idx % HD;
        const float* base = qkv + (size_t)tok * ThreeC + hh * HD + d;
        sq[idx] = base[0] * 0.17677669529663687f;   // 32^-0.5
        sk[idx] = base[Cc];
        sv[idx] = base[2 * Cc];
    }
    if (tid < Ntok) {
        int r = wh * WS + tid / WS, c = ww * WS + tid % WS;
        int hr = (r < Hh - WS) ? 0 : ((r < Hh - SS) ? 1 : 2);
        int wr = (c < Wd - WS) ? 0 : ((c < Wd - SS) ? 1 : 2);
        reg[tid] = hr * 3 + wr;
    }
    __syncthreads();

    for (int idx = tid; idx < Ntok * Ntok; idx += 128) {
        int i = idx / Ntok, j = idx % Ntok;
        float acc = 0.f;
        #pragma unroll
        for (int d = 0; d < HD; d++)
            acc = fmaf(sq[i * HD + d], sk[j * HD + d], acc);
        int dr = i / WS - j / WS + (WS - 1);
        int dc = i % WS - j % WS + (WS - 1);
        acc += rpb[(dr * (2 * WS - 1) + dc) * NHd + hh];
        if (reg[i] != reg[j]) acc -= 100.f;
        sc[idx] = acc;
    }
    __syncthreads();

    if (tid < Ntok) {
        float mx = -1e30f;
        #pragma unroll 7
        for (int j = 0; j < Ntok; j++) mx = fmaxf(mx, sc[tid * Ntok + j]);
        float sum = 0.f;
        #pragma unroll 7
        for (int j = 0; j < Ntok; j++) {
            float e = __expf(sc[tid * Ntok + j] - mx);
            sc[tid * Ntok + j] = e; sum += e;
        }
        float inv = 1.f / sum;
        #pragma unroll 7
        for (int j = 0; j < Ntok; j++) sc[tid * Ntok + j] *= inv;
    }
    __syncthreads();

    for (int idx = tid; idx < Ntok * HD; idx += 128) {
        int i = idx / HD, d = idx % HD;
        float acc = 0.f;
        #pragma unroll 7
        for (int j = 0; j < Ntok; j++)
            acc = fmaf(sc[i * Ntok + j], sv[j * HD + d], acc);
        out[(size_t)(widx * Ntok + i) * Cc + hh * HD + d] = acc;
    }
}

// ---------------- residual + window-reverse + un-shift ----------------
__global__ void k_resid(const float* __restrict__ x, const float* __restrict__ proj,
                        float* __restrict__ x2) {
    size_t i = (size_t)blockIdx.x * 256 + threadIdx.x;
    if (i >= (size_t)Mrows * Cc) return;
    int c = (int)(i % Cc);
    int t = (int)(i / Cc);
    int b = t / (Hh * Wd), p = t % (Hh * Wd);
    int h = p / Wd, w = p % Wd;
    int sh = (h + Hh - SS) % Hh, sw = (w + Wd - SS) % Wd;   // inverse of roll(-SS)
    int wh = sh / WS, ww = sw / WS;
    int tok = ((b * 8 + wh) * 8 + ww) * Ntok + (sh % WS) * WS + (sw % WS);
    x2[i] = x[i] + proj[(size_t)tok * Cc + c];
}

// ---------------- host launch ----------------
extern "C" void kernel_launch(void* const* d_in, const int* in_sizes, int n_in,
                              void* d_out, int out_size) {
    const float* x      = (const float*)d_in[0];
    const float* n1w    = (const float*)d_in[1];
    const float* n1b    = (const float*)d_in[2];
    const float* qkv_w  = (const float*)d_in[3];
    const float* qkv_b  = (const float*)d_in[4];
    const float* rpb    = (const float*)d_in[5];
    const float* proj_w = (const float*)d_in[6];
    const float* proj_b = (const float*)d_in[7];
    const float* n2w    = (const float*)d_in[8];
    const float* n2b    = (const float*)d_in[9];
    const float* fc1_w  = (const float*)d_in[10];
    const float* fc1_b  = (const float*)d_in[11];
    const float* fc2_w  = (const float*)d_in[12];
    const float* fc2_b  = (const float*)d_in[13];
    float* out = (float*)d_out;

    float *p_xw, *p_qkv, *p_att, *p_x2, *p_h, *p_f1;
    cudaGetSymbolAddress((void**)&p_xw,  g_xw);
    cudaGetSymbolAddress((void**)&p_qkv, g_qkv);
    cudaGetSymbolAddress((void**)&p_att, g_att);
    cudaGetSymbolAddress((void**)&p_x2,  g_x2);
    cudaGetSymbolAddress((void**)&p_h,   g_h);
    cudaGetSymbolAddress((void**)&p_f1,  g_f1);

    // 1. LN1 + shift + window partition
    k_ln1<<<Mrows, 128>>>(x, n1w, n1b, p_xw);

    // 2. QKV GEMM: [M,384] @ [384,1152]
    k_gemm<0><<<dim3(ThreeC / 64, Mrows / 64), 256>>>(p_xw, qkv_w, qkv_b, nullptr,
                                                      p_qkv, Mrows, ThreeC, Cc);

    // 3. windowed attention (+rel-pos bias, +shift mask, softmax, AV)
    k_attn<<<(Bn * NWim) * NHd, 128>>>(p_qkv, rpb, p_att);

    // 4. proj GEMM: [M,384] @ [384,384] -> reuse g_xw
    k_gemm<0><<<dim3(Cc / 64, Mrows / 64), 256>>>(p_att, proj_w, proj_b, nullptr,
                                                  p_xw, Mrows, Cc, Cc);

    // 5. residual + window reverse + un-shift
    {
        size_t total = (size_t)Mrows * Cc;
        int blocks = (int)((total + 255) / 256);
        k_resid<<<blocks, 256>>>(x, p_xw, p_x2);
    }

    // 6. LN2
    k_ln2<<<Mrows, 128>>>(p_x2, n2w, n2b, p_h);

    // 7. fc1 GEMM + exact GELU: [M,384] @ [384,1536]
    k_gemm<1><<<dim3(MLPH / 64, Mrows / 64), 256>>>(p_h, fc1_w, fc1_b, nullptr,
                                                    p_f1, Mrows, MLPH, Cc);

    // 8. fc2 GEMM + bias + residual -> d_out: [M,1536] @ [1536,384]
    k_gemm<2><<<dim3(Cc / 64, Mrows / 64), 256>>>(p_f1, fc2_w, fc2_b, p_x2,
                                                  out, Mrows, Cc, MLPH);
}

// round 3
// speedup vs baseline: 2.2156x; 2.2156x over previous
#include <cuda_runtime.h>
#include <math.h>
#include <stdint.h>

// ---------------- problem constants ----------------
constexpr int Bn   = 32;
constexpr int Hh   = 56;
constexpr int Wd   = 56;
constexpr int Cc   = 384;
constexpr int NHd  = 12;
constexpr int WS   = 7;
constexpr int SS   = 3;
constexpr int Ntok = WS * WS;            // 49
constexpr int NWim = (Hh/WS) * (Wd/WS);  // 64
constexpr int HD   = Cc / NHd;           // 32
constexpr int MLPH = 4 * Cc;             // 1536
constexpr int Mrows = Bn * Hh * Wd;      // 100352 tokens
constexpr int ThreeC = 3 * Cc;           // 1152

// ---------------- scratch (device globals; no allocs allowed) ----------------
__device__ float g_xw [(size_t)Mrows * Cc];
__device__ float g_qkv[(size_t)Mrows * ThreeC];
__device__ float g_att[(size_t)Mrows * Cc];
__device__ float g_x2 [(size_t)Mrows * Cc];
__device__ float g_h  [(size_t)Mrows * Cc];
__device__ float g_f1 [(size_t)Mrows * MLPH];

// ---------------- helpers ----------------
__device__ __forceinline__ float f2tf(float x) {
    uint32_t u;
    asm("cvt.rna.tf32.f32 %0, %1;" : "=r"(u) : "f"(x));
    return __uint_as_float(u);
}

__device__ __forceinline__ void mma_tf32(float* d, const uint32_t* a,
                                         const uint32_t* b) {
    asm volatile(
        "mma.sync.aligned.m16n8k8.row.col.f32.tf32.tf32.f32 "
        "{%0,%1,%2,%3}, {%4,%5,%6,%7}, {%8,%9}, {%0,%1,%2,%3};\n"
        : "+f"(d[0]), "+f"(d[1]), "+f"(d[2]), "+f"(d[3])
        : "r"(a[0]), "r"(a[1]), "r"(a[2]), "r"(a[3]),
          "r"(b[0]), "r"(b[1]));
}

// ---------------- block reduce (sum, sumsq) over 128 threads ----------------
__device__ __forceinline__ void blockReduce2(float& s, float& s2) {
    #pragma unroll
    for (int o = 16; o > 0; o >>= 1) {
        s  += __shfl_down_sync(0xFFFFFFFFu, s,  o);
        s2 += __shfl_down_sync(0xFFFFFFFFu, s2, o);
    }
    __shared__ float sh[4][2];
    int w = threadIdx.x >> 5, l = threadIdx.x & 31;
    if (l == 0) { sh[w][0] = s; sh[w][1] = s2; }
    __syncthreads();
    if (threadIdx.x == 0) {
        float a = 0.f, b = 0.f;
        #pragma unroll
        for (int i = 0; i < 4; i++) { a += sh[i][0]; b += sh[i][1]; }
        sh[0][0] = a; sh[0][1] = b;
    }
    __syncthreads();
    s = sh[0][0]; s2 = sh[0][1];
}

// ---------------- kernel 1: LN1 + cyclic shift + window partition ----------------
__global__ void k_ln1(const float* __restrict__ x, const float* __restrict__ w,
                      const float* __restrict__ bi, float* __restrict__ out) {
    int t = blockIdx.x;
    int widx = t / Ntok, n = t % Ntok;
    int b  = widx / NWim, wi = widx % NWim;
    int wh = wi / 8, ww = wi % 8;
    int r  = wh * WS + n / WS, c = ww * WS + n % WS;
    int sh = (r + SS) % Hh, sw = (c + SS) % Wd;
    const float* src = x + ((size_t)b * (Hh*Wd) + sh * Wd + sw) * Cc;

    int tid = threadIdx.x;
    float vals[3]; float s = 0.f, s2 = 0.f;
    #pragma unroll
    for (int i = 0; i < 3; i++) {
        float v = src[tid + i * 128];
        vals[i] = v; s += v; s2 += v * v;
    }
    blockReduce2(s, s2);
    float mean = s * (1.f / Cc);
    float var  = s2 * (1.f / Cc) - mean * mean;
    float inv  = rsqrtf(var + 1e-5f);
    float* dst = out + (size_t)t * Cc;
    #pragma unroll
    for (int i = 0; i < 3; i++) {
        int cI = tid + i * 128;
        dst[cI] = (vals[i] - mean) * inv * w[cI] + bi[cI];
    }
}

// ---------------- kernel: plain LN (for LN2) ----------------
__global__ void k_ln2(const float* __restrict__ x, const float* __restrict__ w,
                      const float* __restrict__ bi, float* __restrict__ out) {
    int t = blockIdx.x;
    const float* src = x + (size_t)t * Cc;
    int tid = threadIdx.x;
    float vals[3]; float s = 0.f, s2 = 0.f;
    #pragma unroll
    for (int i = 0; i < 3; i++) {
        float v = src[tid + i * 128];
        vals[i] = v; s += v; s2 += v * v;
    }
    blockReduce2(s, s2);
    float mean = s * (1.f / Cc);
    float var  = s2 * (1.f / Cc) - mean * mean;
    float inv  = rsqrtf(var + 1e-5f);
    float* dst = out + (size_t)t * Cc;
    #pragma unroll
    for (int i = 0; i < 3; i++) {
        int cI = tid + i * 128;
        dst[cI] = (vals[i] - mean) * inv * w[cI] + bi[cI];
    }
}

// ---------------- tf32 tensor-core GEMM: C = A @ W (+bias, +gelu/residual) ----------
// Block tile 128x128, BK=16, 256 threads = 8 warps (2 M x 4 N), warp tile 64x32.
// EPI: 0 = +bias ; 1 = +bias then exact GELU ; 2 = +bias then +res
template <int EPI>
__global__ __launch_bounds__(256)
void k_gemm_tf32(const float* __restrict__ A, const float* __restrict__ Bm,
                 const float* __restrict__ bias, const float* __restrict__ res,
                 float* __restrict__ Cm, int M, int Ncols, int K) {
    __shared__ float As[128][20];   // [m][k], pad 20 -> conflict-free frag reads
    __shared__ float Bs[16][136];   // [k][n], pad 136 -> conflict-free frag reads

    const int tid  = threadIdx.x;
    const int lane = tid & 31;
    const int warp = tid >> 5;
    const int wm = warp & 1;        // 0..1
    const int wn = warp >> 1;       // 0..3
    const int g = lane >> 2;        // 0..7
    const int q = lane & 3;         // 0..3

    const int row0 = blockIdx.y * 128;
    const int col0 = blockIdx.x * 128;

    float acc[4][4][4];             // [mi][ni][reg]
    #pragma unroll
    for (int i = 0; i < 4; i++)
        #pragma unroll
        for (int j = 0; j < 4; j++)
            #pragma unroll
            for (int r = 0; r < 4; r++) acc[i][j][r] = 0.f;

    // ---- load tile 0 directly into smem ----
    {
        #pragma unroll
        for (int i = 0; i < 2; i++) {
            int f = tid + i * 256;
            int m = f >> 2, kq = (f & 3) * 4;
            float4 a = *(const float4*)&A[(size_t)(row0 + m) * K + kq];
            As[m][kq + 0] = f2tf(a.x); As[m][kq + 1] = f2tf(a.y);
            As[m][kq + 2] = f2tf(a.z); As[m][kq + 3] = f2tf(a.w);
        }
        #pragma unroll
        for (int i = 0; i < 2; i++) {
            int f = tid + i * 256;
            int kr = f >> 5, nq = (f & 31) * 4;
            float4 b = *(const float4*)&Bm[(size_t)kr * Ncols + col0 + nq];
            Bs[kr][nq + 0] = f2tf(b.x); Bs[kr][nq + 1] = f2tf(b.y);
            Bs[kr][nq + 2] = f2tf(b.z); Bs[kr][nq + 3] = f2tf(b.w);
        }
    }
    __syncthreads();

    for (int kt = 0; kt < K; kt += 16) {
        // ---- prefetch next tile into registers ----
        float4 pa[2], pb[2];
        const bool has_next = (kt + 16) < K;
        if (has_next) {
            #pragma unroll
            for (int i = 0; i < 2; i++) {
                int f = tid + i * 256;
                int m = f >> 2, kq = (f & 3) * 4;
                pa[i] = *(const float4*)&A[(size_t)(row0 + m) * K + kt + 16 + kq];
            }
            #pragma unroll
            for (int i = 0; i < 2; i++) {
                int f = tid + i * 256;
                int kr = f >> 5, nq = (f & 31) * 4;
                pb[i] = *(const float4*)&Bm[(size_t)(kt + 16 + kr) * Ncols + col0 + nq];
            }
        }

        // ---- compute on current smem tile ----
        #pragma unroll
        for (int ks = 0; ks < 2; ks++) {
            const int k0 = ks * 8;
            uint32_t af[4][4], bf[4][2];
            #pragma unroll
            for (int mi = 0; mi < 4; mi++) {
                int rbase = wm * 64 + mi * 16 + g;
                af[mi][0] = __float_as_uint(As[rbase    ][k0 + q    ]);
                af[mi][1] = __float_as_uint(As[rbase + 8][k0 + q    ]);
                af[mi][2] = __float_as_uint(As[rbase    ][k0 + q + 4]);
                af[mi][3] = __float_as_uint(As[rbase + 8][k0 + q + 4]);
            }
            #pragma unroll
            for (int ni = 0; ni < 4; ni++) {
                int nbase = wn * 32 + ni * 8 + g;
                bf[ni][0] = __float_as_uint(Bs[k0 + q    ][nbase]);
                bf[ni][1] = __float_as_uint(Bs[k0 + q + 4][nbase]);
            }
            #pragma unroll
            for (int mi = 0; mi < 4; mi++)
                #pragma unroll
                for (int ni = 0; ni < 4; ni++)
                    mma_tf32(acc[mi][ni], af[mi], bf[ni]);
        }
        __syncthreads();

        // ---- commit prefetched tile ----
        if (has_next) {
            #pragma unroll
            for (int i = 0; i < 2; i++) {
                int f = tid + i * 256;
                int m = f >> 2, kq = (f & 3) * 4;
                As[m][kq + 0] = f2tf(pa[i].x); As[m][kq + 1] = f2tf(pa[i].y);
                As[m][kq + 2] = f2tf(pa[i].z); As[m][kq + 3] = f2tf(pa[i].w);
            }
            #pragma unroll
            for (int i = 0; i < 2; i++) {
                int f = tid + i * 256;
                int kr = f >> 5, nq = (f & 31) * 4;
                Bs[kr][nq + 0] = f2tf(pb[i].x); Bs[kr][nq + 1] = f2tf(pb[i].y);
                Bs[kr][nq + 2] = f2tf(pb[i].z); Bs[kr][nq + 3] = f2tf(pb[i].w);
            }
            __syncthreads();
        }
    }

    // ---- epilogue ----
    #pragma unroll
    for (int mi = 0; mi < 4; mi++) {
        int r = row0 + wm * 64 + mi * 16 + g;
        #pragma unroll
        for (int ni = 0; ni < 4; ni++) {
            int c = col0 + wn * 32 + ni * 8 + q * 2;
            float b0 = bias[c], b1 = bias[c + 1];
            float v0 = acc[mi][ni][0] + b0;
            float v1 = acc[mi][ni][1] + b1;
            float v2 = acc[mi][ni][2] + b0;
            float v3 = acc[mi][ni][3] + b1;
            if (EPI == 1) {
                v0 = 0.5f * v0 * (1.f + erff(v0 * 0.70710678118654752f));
                v1 = 0.5f * v1 * (1.f + erff(v1 * 0.70710678118654752f));
                v2 = 0.5f * v2 * (1.f + erff(v2 * 0.70710678118654752f));
                v3 = 0.5f * v3 * (1.f + erff(v3 * 0.70710678118654752f));
            }
            if (EPI == 2) {
                float2 r0 = *(const float2*)&res[(size_t)r * Ncols + c];
                float2 r1 = *(const float2*)&res[(size_t)(r + 8) * Ncols + c];
                v0 += r0.x; v1 += r0.y; v2 += r1.x; v3 += r1.y;
            }
            *(float2*)&Cm[(size_t)r * Ncols + c]       = make_float2(v0, v1);
            *(float2*)&Cm[(size_t)(r + 8) * Ncols + c] = make_float2(v2, v3);
        }
    }
}

// ---------------- attention: one block per (window, head) ----------------
__global__ void k_attn(const float* __restrict__ qkv, const float* __restrict__ rpb,
                       float* __restrict__ out) {
    int blk  = blockIdx.x;
    int widx = blk / NHd, hh = blk % NHd;
    int wi = widx % NWim;
    int wh = wi / 8, ww = wi % 8;

    __shared__ float sq[Ntok * HD], sk[Ntok * HD], sv[Ntok * HD];
    __shared__ float sc[Ntok * Ntok];
    __shared__ int   reg[Ntok];

    int tid = threadIdx.x;
    for (int idx = tid; idx < Ntok * HD; idx += 128) {
        int tok = widx * Ntok + idx / HD;
        int d   = idx % HD;
        const float* base = qkv + (size_t)tok * ThreeC + hh * HD + d;
        sq[idx] = base[0] * 0.17677669529663687f;
        sk[idx] = base[Cc];
        sv[idx] = base[2 * Cc];
    }
    if (tid < Ntok) {
        int r = wh * WS + tid / WS, c = ww * WS + tid % WS;
        int hr = (r < Hh - WS) ? 0 : ((r < Hh - SS) ? 1 : 2);
        int wr = (c < Wd - WS) ? 0 : ((c < Wd - SS) ? 1 : 2);
        reg[tid] = hr * 3 + wr;
    }
    __syncthreads();

    for (int idx = tid; idx < Ntok * Ntok; idx += 128) {
        int i = idx / Ntok, j = idx % Ntok;
        float acc = 0.f;
        #pragma unroll
        for (int d = 0; d < HD; d++)
            acc = fmaf(sq[i * HD + d], sk[j * HD + d], acc);
        int dr = i / WS - j / WS + (WS - 1);
        int dc = i % WS - j % WS + (WS - 1);
        acc += rpb[(dr * (2 * WS - 1) + dc) * NHd + hh];
        if (reg[i] != reg[j]) acc -= 100.f;
        sc[idx] = acc;
    }
    __syncthreads();

    if (tid < Ntok) {
        float mx = -1e30f;
        #pragma unroll 7
        for (int j = 0; j < Ntok; j++) mx = fmaxf(mx, sc[tid * Ntok + j]);
        float sum = 0.f;
        #pragma unroll 7
        for (int j = 0; j < Ntok; j++) {
            float e = __expf(sc[tid * Ntok + j] - mx);
            sc[tid * Ntok + j] = e; sum += e;
        }
        float inv = 1.f / sum;
        #pragma unroll 7
        for (int j = 0; j < Ntok; j++) sc[tid * Ntok + j] *= inv;
    }
    __syncthreads();

    for (int idx = tid; idx < Ntok * HD; idx += 128) {
        int i = idx / HD, d = idx % HD;
        float acc = 0.f;
        #pragma unroll 7
        for (int j = 0; j < Ntok; j++)
            acc = fmaf(sc[i * Ntok + j], sv[j * HD + d], acc);
        out[(size_t)(widx * Ntok + i) * Cc + hh * HD + d] = acc;
    }
}

// ---------------- residual + window-reverse + un-shift ----------------
__global__ void k_resid(const float* __restrict__ x, const float* __restrict__ proj,
                        float* __restrict__ x2) {
    size_t i = (size_t)blockIdx.x * 256 + threadIdx.x;
    if (i >= (size_t)Mrows * Cc) return;
    int c = (int)(i % Cc);
    int t = (int)(i / Cc);
    int b = t / (Hh * Wd), p = t % (Hh * Wd);
    int h = p / Wd, w = p % Wd;
    int sh = (h + Hh - SS) % Hh, sw = (w + Wd - SS) % Wd;
    int wh = sh / WS, ww = sw / WS;
    int tok = ((b * 8 + wh) * 8 + ww) * Ntok + (sh % WS) * WS + (sw % WS);
    x2[i] = x[i] + proj[(size_t)tok * Cc + c];
}

// ---------------- host launch ----------------
extern "C" void kernel_launch(void* const* d_in, const int* in_sizes, int n_in,
                              void* d_out, int out_size) {
    const float* x      = (const float*)d_in[0];
    const float* n1w    = (const float*)d_in[1];
    const float* n1b    = (const float*)d_in[2];
    const float* qkv_w  = (const float*)d_in[3];
    const float* qkv_b  = (const float*)d_in[4];
    const float* rpb    = (const float*)d_in[5];
    const float* proj_w = (const float*)d_in[6];
    const float* proj_b = (const float*)d_in[7];
    const float* n2w    = (const float*)d_in[8];
    const float* n2b    = (const float*)d_in[9];
    const float* fc1_w  = (const float*)d_in[10];
    const float* fc1_b  = (const float*)d_in[11];
    const float* fc2_w  = (const float*)d_in[12];
    const float* fc2_b  = (const float*)d_in[13];
    float* out = (float*)d_out;

    float *p_xw, *p_qkv, *p_att, *p_x2, *p_h, *p_f1;
    cudaGetSymbolAddress((void**)&p_xw,  g_xw);
    cudaGetSymbolAddress((void**)&p_qkv, g_qkv);
    cudaGetSymbolAddress((void**)&p_att, g_att);
    cudaGetSymbolAddress((void**)&p_x2,  g_x2);
    cudaGetSymbolAddress((void**)&p_h,   g_h);
    cudaGetSymbolAddress((void**)&p_f1,  g_f1);

    // 1. LN1 + shift + window partition
    k_ln1<<<Mrows, 128>>>(x, n1w, n1b, p_xw);

    // 2. QKV GEMM: [M,384] @ [384,1152]
    k_gemm_tf32<0><<<dim3(ThreeC / 128, Mrows / 128), 256>>>(
        p_xw, qkv_w, qkv_b, nullptr, p_qkv, Mrows, ThreeC, Cc);

    // 3. windowed attention
    k_attn<<<(Bn * NWim) * NHd, 128>>>(p_qkv, rpb, p_att);

    // 4. proj GEMM: [M,384] @ [384,384]
    k_gemm_tf32<0><<<dim3(Cc / 128, Mrows / 128), 256>>>(
        p_att, proj_w, proj_b, nullptr, p_xw, Mrows, Cc, Cc);

    // 5. residual + window reverse + un-shift
    {
        size_t total = (size_t)Mrows * Cc;
        int blocks = (int)((total + 255) / 256);
        k_resid<<<blocks, 256>>>(x, p_xw, p_x2);
    }

    // 6. LN2
    k_ln2<<<Mrows, 128>>>(p_x2, n2w, n2b, p_h);

    // 7. fc1 GEMM + exact GELU: [M,384] @ [384,1536]
    k_gemm_tf32<1><<<dim3(MLPH / 128, Mrows / 128), 256>>>(
        p_h, fc1_w, fc1_b, nullptr, p_f1, Mrows, MLPH, Cc);

    // 8. fc2 GEMM + bias + residual -> d_out: [M,1536] @ [1536,384]
    k_gemm_tf32<2><<<dim3(Cc / 128, Mrows / 128), 256>>>(
        p_f1, fc2_w, fc2_b, p_x2, out, Mrows, Cc, MLPH);
}

// round 5
// speedup vs baseline: 3.4267x; 1.5467x over previous
#include <cuda_runtime.h>
#include <math.h>
#include <stdint.h>

// ---------------- problem constants ----------------
constexpr int Bn   = 32;
constexpr int Hh   = 56;
constexpr int Wd   = 56;
constexpr int Cc   = 384;
constexpr int NHd  = 12;
constexpr int WS   = 7;
constexpr int SS   = 3;
constexpr int Ntok = WS * WS;            // 49
constexpr int NWim = (Hh/WS) * (Wd/WS);  // 64
constexpr int HD   = Cc / NHd;           // 32
constexpr int MLPH = 4 * Cc;             // 1536
constexpr int Mrows = Bn * Hh * Wd;      // 100352 tokens
constexpr int ThreeC = 3 * Cc;           // 1152

// ---------------- scratch (device globals; no allocs allowed) ----------------
__device__ float g_xw [(size_t)Mrows * Cc];
__device__ float g_qkv[(size_t)Mrows * ThreeC];
__device__ float g_att[(size_t)Mrows * Cc];
__device__ float g_x2 [(size_t)Mrows * Cc];
__device__ float g_h  [(size_t)Mrows * Cc];
__device__ float g_f1 [(size_t)Mrows * MLPH];
// transposed (+tf32-rounded) weights [N,K]: qkv | proj | fc1 | fc2
constexpr size_t WT_QKV  = 0;
constexpr size_t WT_PROJ = WT_QKV  + (size_t)Cc * ThreeC;
constexpr size_t WT_FC1  = WT_PROJ + (size_t)Cc * Cc;
constexpr size_t WT_FC2  = WT_FC1  + (size_t)Cc * MLPH;
__device__ float g_wt[WT_FC2 + (size_t)MLPH * Cc];

// ---------------- helpers ----------------
__device__ __forceinline__ float f2tf(float x) {
    uint32_t u;
    asm("cvt.rna.tf32.f32 %0, %1;" : "=r"(u) : "f"(x));
    return __uint_as_float(u);
}
__device__ __forceinline__ uint32_t smem_u32(const void* p) {
    uint32_t a;
    asm("{ .reg .u64 t; cvta.to.shared.u64 t, %1; cvt.u32.u64 %0, t; }" : "=r"(a) : "l"(p));
    return a;
}
#define CP16(dst, src) asm volatile("cp.async.cg.shared.global [%0], [%1], 16;\n" :: "r"(dst), "l"(src))
#define CP_COMMIT()    asm volatile("cp.async.commit_group;\n" ::: "memory")
#define CP_WAIT1()     asm volatile("cp.async.wait_group 1;\n" ::: "memory")

__device__ __forceinline__ void mma_tf32(float* d, const uint32_t* a,
                                         const uint32_t* b) {
    asm volatile(
        "mma.sync.aligned.m16n8k8.row.col.f32.tf32.tf32.f32 "
        "{%0,%1,%2,%3}, {%4,%5,%6,%7}, {%8,%9}, {%0,%1,%2,%3};\n"
        : "+f"(d[0]), "+f"(d[1]), "+f"(d[2]), "+f"(d[3])
        : "r"(a[0]), "r"(a[1]), "r"(a[2]), "r"(a[3]),
          "r"(b[0]), "r"(b[1]));
}

// ---------------- weight transpose + tf32 round: W[K,N] -> Wt[N,K] ----------------
__global__ void k_transpose(const float* __restrict__ W, float* __restrict__ Wt,
                            int K, int N) {
    __shared__ float t[32][33];
    int k0 = blockIdx.y * 32, n0 = blockIdx.x * 32;
    int tx = threadIdx.x, ty = threadIdx.y;
    #pragma unroll
    for (int i = 0; i < 32; i += 8)
        t[ty + i][tx] = W[(size_t)(k0 + ty + i) * N + n0 + tx];
    __syncthreads();
    #pragma unroll
    for (int i = 0; i < 32; i += 8)
        Wt[(size_t)(n0 + ty + i) * K + k0 + tx] = f2tf(t[tx][ty + i]);
}

// ---------------- tf32 mma.sync GEMM, cp.async 3-stage ----------------
// Block 128x128, BK=16, 256 thr = 8 warps (2M x 4N), warp tile 64x32.
// Both operands K-major in smem: [row][20] padded (conflict-free frag reads).
// EPI: 0 = +bias ; 1 = +bias,GELU,tf32-round ; 2 = +bias,+res
constexpr int NSTAGE = 3;
constexpr int STAGEF = 128 * 20;               // floats per operand per stage
constexpr int STAGEB = STAGEF * 2 * 4;         // bytes per stage (A+B) = 20480
constexpr int SMEM_DYN = NSTAGE * STAGEB;      // 61440

template <int EPI>
__global__ __launch_bounds__(256)
void k_gemm_tc(const float* __restrict__ A, const float* __restrict__ Wt,
               const float* __restrict__ bias, const float* __restrict__ res,
               float* __restrict__ Cm, int M, int N, int K) {
    extern __shared__ float smemf[];
    uint32_t sbase = smem_u32(smemf);

    const int tid  = threadIdx.x;
    const int lane = tid & 31, warp = tid >> 5;
    const int wm = warp & 1, wn = warp >> 1;
    const int g = lane >> 2, q = lane & 3;
    const int row0 = blockIdx.y * 128, col0 = blockIdx.x * 128;
    const int KT = K / 16;

    const float* Ab = A  + (size_t)row0 * K;
    const float* Bb = Wt + (size_t)col0 * K;

    float acc[4][4][4];
    #pragma unroll
    for (int i = 0; i < 4; i++)
        #pragma unroll
        for (int j = 0; j < 4; j++)
            #pragma unroll
            for (int r = 0; r < 4; r++) acc[i][j][r] = 0.f;

    auto load_stage = [&](int kt, int s) {
        uint32_t stA = sbase + (uint32_t)s * STAGEB;
        uint32_t stB = stA + STAGEF * 4;
        const float* Ap = Ab + kt * 16;
        const float* Bp = Bb + kt * 16;
        #pragma unroll
        for (int i = 0; i < 2; i++) {
            int c = tid + i * 256, m = c >> 2, kq = (c & 3) * 4;
            CP16(stA + (uint32_t)(m * 20 + kq) * 4, Ap + (size_t)m * K + kq);
        }
        #pragma unroll
        for (int i = 0; i < 2; i++) {
            int c = tid + i * 256, n = c >> 2, kq = (c & 3) * 4;
            CP16(stB + (uint32_t)(n * 20 + kq) * 4, Bp + (size_t)n * K + kq);
        }
    };

    load_stage(0, 0); CP_COMMIT();
    load_stage(1, 1); CP_COMMIT();

    for (int kt = 0; kt < KT; kt++) {
        CP_WAIT1();
        __syncthreads();
        const float* As = smemf + (kt % 3) * (STAGEF * 2);
        const float* Bs = As + STAGEF;
        #pragma unroll
        for (int ks = 0; ks < 2; ks++) {
            const int k0 = ks * 8;
            uint32_t af[4][4], bf[4][2];
            #pragma unroll
            for (int mi = 0; mi < 4; mi++) {
                int rb = wm * 64 + mi * 16 + g;
                af[mi][0] = __float_as_uint(As[rb * 20 + k0 + q]);
                af[mi][1] = __float_as_uint(As[(rb + 8) * 20 + k0 + q]);
                af[mi][2] = __float_as_uint(As[rb * 20 + k0 + q + 4]);
                af[mi][3] = __float_as_uint(As[(rb + 8) * 20 + k0 + q + 4]);
            }
            #pragma unroll
            for (int ni = 0; ni < 4; ni++) {
                int nb = wn * 32 + ni * 8 + g;
                bf[ni][0] = __float_as_uint(Bs[nb * 20 + k0 + q]);
                bf[ni][1] = __float_as_uint(Bs[nb * 20 + k0 + q + 4]);
            }
            #pragma unroll
            for (int mi = 0; mi < 4; mi++)
                #pragma unroll
                for (int ni = 0; ni < 4; ni++)
                    mma_tf32(acc[mi][ni], af[mi], bf[ni]);
        }
        if (kt + 2 < KT) load_stage(kt + 2, (kt + 2) % 3);
        CP_COMMIT();
    }

    // ---- epilogue ----
    #pragma unroll
    for (int mi = 0; mi < 4; mi++) {
        int r = row0 + wm * 64 + mi * 16 + g;
        #pragma unroll
        for (int ni = 0; ni < 4; ni++) {
            int c = col0 + wn * 32 + ni * 8 + q * 2;
            float b0 = bias[c], b1 = bias[c + 1];
            float v0 = acc[mi][ni][0] + b0;
            float v1 = acc[mi][ni][1] + b1;
            float v2 = acc[mi][ni][2] + b0;
            float v3 = acc[mi][ni][3] + b1;
            if (EPI == 1) {
                v0 = f2tf(0.5f * v0 * (1.f + erff(v0 * 0.70710678118654752f)));
                v1 = f2tf(0.5f * v1 * (1.f + erff(v1 * 0.70710678118654752f)));
                v2 = f2tf(0.5f * v2 * (1.f + erff(v2 * 0.70710678118654752f)));
                v3 = f2tf(0.5f * v3 * (1.f + erff(v3 * 0.70710678118654752f)));
            }
            if (EPI == 2) {
                float2 r0 = *(const float2*)&res[(size_t)r * N + c];
                float2 r1 = *(const float2*)&res[(size_t)(r + 8) * N + c];
                v0 += r0.x; v1 += r0.y; v2 += r1.x; v3 += r1.y;
            }
            *(float2*)&Cm[(size_t)r * N + c]       = make_float2(v0, v1);
            *(float2*)&Cm[(size_t)(r + 8) * N + c] = make_float2(v2, v3);
        }
    }
}

// ---------------- block reduce (sum, sumsq) over 128 threads ----------------
__device__ __forceinline__ void blockReduce2(float& s, float& s2) {
    #pragma unroll
    for (int o = 16; o > 0; o >>= 1) {
        s  += __shfl_down_sync(0xFFFFFFFFu, s,  o);
        s2 += __shfl_down_sync(0xFFFFFFFFu, s2, o);
    }
    __shared__ float sh[4][2];
    int w = threadIdx.x >> 5, l = threadIdx.x & 31;
    if (l == 0) { sh[w][0] = s; sh[w][1] = s2; }
    __syncthreads();
    if (threadIdx.x == 0) {
        float a = 0.f, b = 0.f;
        #pragma unroll
        for (int i = 0; i < 4; i++) { a += sh[i][0]; b += sh[i][1]; }
        sh[0][0] = a; sh[0][1] = b;
    }
    __syncthreads();
    s = sh[0][0]; s2 = sh[0][1];
}

// ---------------- LN1 + shift + window partition (tf32-rounded out) ----------------
__global__ void k_ln1(const float* __restrict__ x, const float* __restrict__ w,
                      const float* __restrict__ bi, float* __restrict__ out) {
    int t = blockIdx.x;
    int widx = t / Ntok, n = t % Ntok;
    int b  = widx / NWim, wi = widx % NWim;
    int wh = wi / 8, ww = wi % 8;
    int r  = wh * WS + n / WS, c = ww * WS + n % WS;
    int sh = (r + SS) % Hh, sw = (c + SS) % Wd;
    const float* src = x + ((size_t)b * (Hh*Wd) + sh * Wd + sw) * Cc;

    int tid = threadIdx.x;
    float vals[3]; float s = 0.f, s2 = 0.f;
    #pragma unroll
    for (int i = 0; i < 3; i++) {
        float v = src[tid + i * 128];
        vals[i] = v; s += v; s2 += v * v;
    }
    blockReduce2(s, s2);
    float mean = s * (1.f / Cc);
    float var  = s2 * (1.f / Cc) - mean * mean;
    float inv  = rsqrtf(var + 1e-5f);
    float* dst = out + (size_t)t * Cc;
    #pragma unroll
    for (int i = 0; i < 3; i++) {
        int cI = tid + i * 128;
        dst[cI] = f2tf((vals[i] - mean) * inv * w[cI] + bi[cI]);
    }
}

// ---------------- fused: residual(+window-reverse+unshift) then LN2 ----------------
__global__ void k_resid_ln2(const float* __restrict__ x, const float* __restrict__ proj,
                            const float* __restrict__ w, const float* __restrict__ bi,
                            float* __restrict__ x2, float* __restrict__ hout) {
    int t = blockIdx.x;
    int b = t / (Hh * Wd), p = t % (Hh * Wd);
    int h = p / Wd, ww0 = p % Wd;
    int sh = (h + Hh - SS) % Hh, sw = (ww0 + Wd - SS) % Wd;
    int wh = sh / WS, ww = sw / WS;
    int tok = ((b * 8 + wh) * 8 + ww) * Ntok + (sh % WS) * WS + (sw % WS);
    const float* src1 = x    + (size_t)t   * Cc;
    const float* src2 = proj + (size_t)tok * Cc;

    int tid = threadIdx.x;
    float vals[3]; float s = 0.f, s2 = 0.f;
    #pragma unroll
    for (int i = 0; i < 3; i++) {
        int cI = tid + i * 128;
        float v = src1[cI] + src2[cI];
        vals[i] = v; s += v; s2 += v * v;
    }
    blockReduce2(s, s2);
    float mean = s * (1.f / Cc);
    float var  = s2 * (1.f / Cc) - mean * mean;
    float inv  = rsqrtf(var + 1e-5f);
    float* d1 = x2   + (size_t)t * Cc;
    float* d2 = hout + (size_t)t * Cc;
    #pragma unroll
    for (int i = 0; i < 3; i++) {
        int cI = tid + i * 128;
        d1[cI] = vals[i];
        d2[cI] = f2tf((vals[i] - mean) * inv * w[cI] + bi[cI]);
    }
}

// ---------------- attention: register-tiled, one block per (window, head) -------
constexpr int SCP = 52;  // padded row stride for score matrix / token arrays
__global__ __launch_bounds__(128)
void k_attn(const float* __restrict__ qkv, const float* __restrict__ rpb,
            float* __restrict__ out) {
    int blk  = blockIdx.x;
    int widx = blk / NHd, hh = blk % NHd;
    int wi = widx % NWim;
    int wh = wi / 8, ww = wi % 8;

    __shared__ float sq[SCP * HD], sk[SCP * HD], sv[SCP * HD];
    __shared__ float sc[SCP * SCP];
    __shared__ float sbias[169];
    __shared__ int   reg[Ntok];

    int tid = threadIdx.x;
    // load q (scaled), k, v as float4 chunks: 49*32/4 = 392 chunks each
    for (int idx = tid; idx < 392; idx += 128) {
        int row = idx >> 3, d4 = (idx & 7) * 4;
        const float* base = qkv + (size_t)(widx * Ntok + row) * ThreeC + hh * HD + d4;
        float4 qv = *(const float4*)(base);
        float4 kv = *(const float4*)(base + Cc);
        float4 vv = *(const float4*)(base + 2 * Cc);
        const float sc0 = 0.17677669529663687f;
        qv.x *= sc0; qv.y *= sc0; qv.z *= sc0; qv.w *= sc0;
        *(float4*)&sq[row * HD + d4] = qv;
        *(float4*)&sk[row * HD + d4] = kv;
        *(float4*)&sv[row * HD + d4] = vv;
    }
    if (tid < Ntok) {
        int r = wh * WS + tid / WS, c = ww * WS + tid % WS;
        int hr = (r < Hh - WS) ? 0 : ((r < Hh - SS) ? 1 : 2);
        int wr = (c < Wd - WS) ? 0 : ((c < Wd - SS) ? 1 : 2);
        reg[tid] = hr * 3 + wr;
    }
    if (tid < 128) {
        for (int idx = tid; idx < 169; idx += 128)
            sbias[idx] = rpb[idx * NHd + hh];
    }
    __syncthreads();

    // QK^T: 13x13 grid of 4x4 tiles
    for (int t = tid; t < 169; t += 128) {
        int i0 = (t / 13) * 4, j0 = (t % 13) * 4;
        float a4[4][4];
        #pragma unroll
        for (int r = 0; r < 4; r++)
            #pragma unroll
            for (int c = 0; c < 4; c++) a4[r][c] = 0.f;
        #pragma unroll
        for (int dv = 0; dv < 8; dv++) {
            float4 qr[4], kr[4];
            #pragma unroll
            for (int r = 0; r < 4; r++) qr[r] = *(const float4*)&sq[(i0 + r) * HD + dv * 4];
            #pragma unroll
            for (int c = 0; c < 4; c++) kr[c] = *(const float4*)&sk[(j0 + c) * HD + dv * 4];
            #pragma unroll
            for (int r = 0; r < 4; r++)
                #pragma unroll
                for (int c = 0; c < 4; c++) {
                    a4[r][c] = fmaf(qr[r].x, kr[c].x, a4[r][c]);
                    a4[r][c] = fmaf(qr[r].y, kr[c].y, a4[r][c]);
                    a4[r][c] = fmaf(qr[r].z, kr[c].z, a4[r][c]);
                    a4[r][c] = fmaf(qr[r].w, kr[c].w, a4[r][c]);
                }
        }
        #pragma unroll
        for (int r = 0; r < 4; r++) {
            int i = i0 + r;
            if (i >= Ntok) break;
            #pragma unroll
            for (int c = 0; c < 4; c++) {
                int j = j0 + c;
                if (j >= Ntok) continue;
                int dr = i / WS - j / WS + (WS - 1);
                int dc = i % WS - j % WS + (WS - 1);
                float v = a4[r][c] + sbias[dr * 13 + dc];
                if (reg[i] != reg[j]) v -= 100.f;
                sc[i * SCP + j] = v;
            }
        }
    }
    __syncthreads();

    // softmax per row (49 active threads)
    if (tid < Ntok) {
        float* row = &sc[tid * SCP];
        float mx = row[48];
        #pragma unroll
        for (int j4 = 0; j4 < 48; j4 += 4) {
            float4 v = *(const float4*)&row[j4];
            mx = fmaxf(mx, fmaxf(fmaxf(v.x, v.y), fmaxf(v.z, v.w)));
        }
        float sum = __expf(row[48] - mx);
        row[48] = sum;
        #pragma unroll
        for (int j4 = 0; j4 < 48; j4 += 4) {
            float4 v = *(const float4*)&row[j4];
            v.x = __expf(v.x - mx); v.y = __expf(v.y - mx);
            v.z = __expf(v.z - mx); v.w = __expf(v.w - mx);
            sum += v.x + v.y + v.z + v.w;
            *(float4*)&row[j4] = v;
        }
        float inv = 1.f / sum;
        row[48] *= inv;
        #pragma unroll
        for (int j4 = 0; j4 < 48; j4 += 4) {
            float4 v = *(const float4*)&row[j4];
            v.x *= inv; v.y *= inv; v.z *= inv; v.w *= inv;
            *(float4*)&row[j4] = v;
        }
    }
    __syncthreads();

    // AV: 13 i-tiles x 8 d-tiles = 104 tiles of 4x4
    if (tid < 104) {
        int i0 = (tid / 8) * 4, d0 = (tid % 8) * 4;
        float a4[4][4];
        #pragma unroll
        for (int r = 0; r < 4; r++)
            #pragma unroll
            for (int c = 0; c < 4; c++) a4[r][c] = 0.f;
        for (int j0 = 0; j0 < 48; j0 += 4) {
            float4 s4[4], v4[4];
            #pragma unroll
            for (int r = 0; r < 4; r++) s4[r] = *(const float4*)&sc[(i0 + r) * SCP + j0];
            #pragma unroll
            for (int c = 0; c < 4; c++) v4[c] = *(const float4*)&sv[(j0 + c) * HD + d0];
            #pragma unroll
            for (int r = 0; r < 4; r++) {
                #pragma unroll
                for (int c = 0; c < 4; c++) {
                    float acc = a4[r][c];
                    acc = fmaf(s4[r].x, (&v4[0].x)[c], acc);
                    acc = fmaf(s4[r].y, (&v4[1].x)[c], acc);
                    acc = fmaf(s4[r].z, (&v4[2].x)[c], acc);
                    acc = fmaf(s4[r].w, (&v4[3].x)[c], acc);
                    a4[r][c] = acc;
                }
            }
        }
        {   // j = 48 remainder
            float4 v4 = *(const float4*)&sv[48 * HD + d0];
            #pragma unroll
            for (int r = 0; r < 4; r++) {
                float s = sc[(i0 + r) * SCP + 48];
                a4[r][0] = fmaf(s, v4.x, a4[r][0]);
                a4[r][1] = fmaf(s, v4.y, a4[r][1]);
                a4[r][2] = fmaf(s, v4.z, a4[r][2]);
                a4[r][3] = fmaf(s, v4.w, a4[r][3]);
            }
        }
        #pragma unroll
        for (int r = 0; r < 4; r++) {
            int i = i0 + r;
            if (i >= Ntok) break;
            float4 o;
            o.x = f2tf(a4[r][0]); o.y = f2tf(a4[r][1]);
            o.z = f2tf(a4[r][2]); o.w = f2tf(a4[r][3]);
            *(float4*)&out[(size_t)(widx * Ntok + i) * Cc + hh * HD + d0] = o;
        }
    }
}

// ---------------- host launch ----------------
extern "C" void kernel_launch(void* const* d_in, const int* in_sizes, int n_in,
                              void* d_out, int out_size) {
    const float* x      = (const float*)d_in[0];
    const float* n1w    = (const float*)d_in[1];
    const float* n1b    = (const float*)d_in[2];
    const float* qkv_w  = (const float*)d_in[3];
    const float* qkv_b  = (const float*)d_in[4];
    const float* rpb    = (const float*)d_in[5];
    const float* proj_w = (const float*)d_in[6];
    const float* proj_b = (const float*)d_in[7];
    const float* n2w    = (const float*)d_in[8];
    const float* n2b    = (const float*)d_in[9];
    const float* fc1_w  = (const float*)d_in[10];
    const float* fc1_b  = (const float*)d_in[11];
    const float* fc2_w  = (const float*)d_in[12];
    const float* fc2_b  = (const float*)d_in[13];
    float* out = (float*)d_out;

    float *p_xw, *p_qkv, *p_att, *p_x2, *p_h, *p_f1, *p_wt;
    cudaGetSymbolAddress((void**)&p_xw,  g_xw);
    cudaGetSymbolAddress((void**)&p_qkv, g_qkv);
    cudaGetSymbolAddress((void**)&p_att, g_att);
    cudaGetSymbolAddress((void**)&p_x2,  g_x2);
    cudaGetSymbolAddress((void**)&p_h,   g_h);
    cudaGetSymbolAddress((void**)&p_f1,  g_f1);
    cudaGetSymbolAddress((void**)&p_wt,  g_wt);

    cudaFuncSetAttribute(k_gemm_tc<0>, cudaFuncAttributeMaxDynamicSharedMemorySize, SMEM_DYN);
    cudaFuncSetAttribute(k_gemm_tc<1>, cudaFuncAttributeMaxDynamicSharedMemorySize, SMEM_DYN);
    cudaFuncSetAttribute(k_gemm_tc<2>, cudaFuncAttributeMaxDynamicSharedMemorySize, SMEM_DYN);

    // 0. transpose + tf32-round weights to [N,K]
    k_transpose<<<dim3(ThreeC/32, Cc/32), dim3(32,8)>>>(qkv_w,  p_wt + WT_QKV,  Cc, ThreeC);
    k_transpose<<<dim3(Cc/32,    Cc/32), dim3(32,8)>>>(proj_w, p_wt + WT_PROJ, Cc, Cc);
    k_transpose<<<dim3(MLPH/32,  Cc/32), dim3(32,8)>>>(fc1_w,  p_wt + WT_FC1,  Cc, MLPH);
    k_transpose<<<dim3(Cc/32,  MLPH/32), dim3(32,8)>>>(fc2_w,  p_wt + WT_FC2,  MLPH, Cc);

    // 1. LN1 + shift + window partition
    k_ln1<<<Mrows, 128>>>(x, n1w, n1b, p_xw);

    // 2. QKV GEMM
    k_gemm_tc<0><<<dim3(ThreeC/128, Mrows/128), 256, SMEM_DYN>>>(
        p_xw, p_wt + WT_QKV, qkv_b, nullptr, p_qkv, Mrows, ThreeC, Cc);

    // 3. windowed attention
    k_attn<<<(Bn * NWim) * NHd, 128>>>(p_qkv, rpb, p_att);

    // 4. proj GEMM
    k_gemm_tc<0><<<dim3(Cc/128, Mrows/128), 256, SMEM_DYN>>>(
        p_att, p_wt + WT_PROJ, proj_b, nullptr, p_xw, Mrows, Cc, Cc);

    // 5+6. residual + window reverse + un-shift, fused with LN2
    k_resid_ln2<<<Mrows, 128>>>(x, p_xw, n2w, n2b, p_x2, p_h);

    // 7. fc1 GEMM + GELU (+tf32 round)
    k_gemm_tc<1><<<dim3(MLPH/128, Mrows/128), 256, SMEM_DYN>>>(
        p_h, p_wt + WT_FC1, fc1_b, nullptr, p_f1, Mrows, MLPH, Cc);

    // 8. fc2 GEMM + bias + residual -> out
    k_gemm_tc<2><<<dim3(Cc/128, Mrows/128), 256, SMEM_DYN>>>(
        p_f1, p_wt + WT_FC2, fc2_b, p_x2, out, Mrows, Cc, MLPH);
}

// round 6
// speedup vs baseline: 5.2519x; 1.5326x over previous
#include <cuda_runtime.h>
#include <cuda_bf16.h>
#include <math.h>
#include <stdint.h>

// ---------------- problem constants ----------------
constexpr int Bn   = 32;
constexpr int Hh   = 56;
constexpr int Wd   = 56;
constexpr int Cc   = 384;
constexpr int NHd  = 12;
constexpr int WS   = 7;
constexpr int SS   = 3;
constexpr int Ntok = WS * WS;            // 49
constexpr int NWim = (Hh/WS) * (Wd/WS);  // 64
constexpr int HD   = Cc / NHd;           // 32
constexpr int MLPH = 4 * Cc;             // 1536
constexpr int Mrows = Bn * Hh * Wd;      // 100352
constexpr int ThreeC = 3 * Cc;           // 1152

// ---------------- scratch (device globals) ----------------
__device__ __nv_bfloat16 g_xw  [(size_t)Mrows * Cc];      // ln1 out
__device__ __nv_bfloat16 g_qkv [(size_t)Mrows * ThreeC];  // qkv gemm out
__device__ __nv_bfloat16 g_attb[(size_t)Mrows * Cc];      // attn out
__device__ float         g_proj[(size_t)Mrows * Cc];      // proj gemm out (f32)
__device__ float         g_x2  [(size_t)Mrows * Cc];      // residual carrier
__device__ __nv_bfloat16 g_h   [(size_t)Mrows * Cc];      // ln2 out
__device__ __nv_bfloat16 g_f1  [(size_t)Mrows * MLPH];    // fc1+gelu out
// transposed bf16 weights [N,K]
constexpr size_t WT_QKV  = 0;
constexpr size_t WT_PROJ = WT_QKV  + (size_t)Cc * ThreeC;
constexpr size_t WT_FC1  = WT_PROJ + (size_t)Cc * Cc;
constexpr size_t WT_FC2  = WT_FC1  + (size_t)Cc * MLPH;
__device__ __nv_bfloat16 g_wt[WT_FC2 + (size_t)MLPH * Cc];

// ---------------- helpers ----------------
__device__ __forceinline__ uint32_t smem_u32(const void* p) {
    uint32_t a;
    asm("{ .reg .u64 t; cvta.to.shared.u64 t, %1; cvt.u32.u64 %0, t; }" : "=r"(a) : "l"(p));
    return a;
}
#define CP16(dst, src) asm volatile("cp.async.cg.shared.global [%0], [%1], 16;\n" :: "r"(dst), "l"(src))
#define CP_COMMIT()    asm volatile("cp.async.commit_group;\n" ::: "memory")
#define CP_WAIT2()     asm volatile("cp.async.wait_group 2;\n" ::: "memory")

__device__ __forceinline__ uint32_t swz64(uint32_t off) {
    return off ^ ((off >> 3) & 0x30);
}
__device__ __forceinline__ uint32_t lds32(uint32_t addr) {
    uint32_t v;
    asm volatile("ld.shared.b32 %0, [%1];" : "=r"(v) : "r"(addr));
    return v;
}
__device__ __forceinline__ void mma_bf16(float* d, const uint32_t* a, const uint32_t* b) {
    asm volatile(
        "mma.sync.aligned.m16n8k16.row.col.f32.bf16.bf16.f32 "
        "{%0,%1,%2,%3}, {%4,%5,%6,%7}, {%8,%9}, {%0,%1,%2,%3};\n"
        : "+f"(d[0]), "+f"(d[1]), "+f"(d[2]), "+f"(d[3])
        : "r"(a[0]), "r"(a[1]), "r"(a[2]), "r"(a[3]), "r"(b[0]), "r"(b[1]));
}
__device__ __forceinline__ __nv_bfloat162 pack_bf2(float a, float b) {
    return __floats2bfloat162_rn(a, b);
}

// ---------------- weight transpose + bf16: W[K,N] -> Wt[N,K] ----------------
__global__ void k_transpose(const float* __restrict__ W, __nv_bfloat16* __restrict__ Wt,
                            int K, int N) {
    __shared__ float t[32][33];
    int k0 = blockIdx.y * 32, n0 = blockIdx.x * 32;
    int tx = threadIdx.x, ty = threadIdx.y;
    #pragma unroll
    for (int i = 0; i < 32; i += 8)
        t[ty + i][tx] = W[(size_t)(k0 + ty + i) * N + n0 + tx];
    __syncthreads();
    #pragma unroll
    for (int i = 0; i < 32; i += 8)
        Wt[(size_t)(n0 + ty + i) * K + k0 + tx] = __float2bfloat16_rn(t[tx][ty + i]);
}

// ---------------- bf16 mma.sync GEMM ----------------
// CTA 256x128, BK=32, 8 warps (4M x 2N), warp tile 64x64.
// smem: 64B rows, SW64 swizzle. 4-stage cp.async.
// OT: 0 = bias, bf16 out ; 1 = bias+gelu, bf16 out ; 2 = bias, f32 out ; 3 = bias+res, f32 out
constexpr int GBM = 256, GBN = 128;
constexpr int ASTB = GBM * 64;            // 16384
constexpr int BSTB = GBN * 64;            // 8192
constexpr int STB  = ASTB + BSTB;         // 24576
constexpr int NST  = 4;
constexpr int SMEM_GEMM = NST * STB;      // 98304

template <int OT, typename OutT>
__global__ __launch_bounds__(256, 1)
void k_gemm_bf(const __nv_bfloat16* __restrict__ A, const __nv_bfloat16* __restrict__ Wt,
               const float* __restrict__ bias, const float* __restrict__ res,
               OutT* __restrict__ Cm, int M, int N, int K) {
    extern __shared__ char smem[];
    uint32_t sbase = smem_u32(smem);

    const int tid  = threadIdx.x;
    const int lane = tid & 31, warp = tid >> 5;
    const int wm = warp & 3, wn = warp >> 2;       // 4 M-warps x 2 N-warps
    const int g = lane >> 2, q = lane & 3;
    const int row0 = blockIdx.y * GBM, col0 = blockIdx.x * GBN;
    const int KT = K / 32;

    const __nv_bfloat16* Ab = A  + (size_t)row0 * K;
    const __nv_bfloat16* Bb = Wt + (size_t)col0 * K;

    float acc[4][8][4];
    #pragma unroll
    for (int i = 0; i < 4; i++)
        #pragma unroll
        for (int j = 0; j < 8; j++)
            #pragma unroll
            for (int r = 0; r < 4; r++) acc[i][j][r] = 0.f;

    auto load_stage = [&](int kt, int s) {
        uint32_t sA = sbase + (uint32_t)s * STB;
        uint32_t sB = sA + ASTB;
        const __nv_bfloat16* Ap = Ab + kt * 32;
        const __nv_bfloat16* Bp = Bb + kt * 32;
        #pragma unroll
        for (int i = 0; i < 4; i++) {          // A: 1024 chunks
            int c = tid + i * 256, r = c >> 2, cc = c & 3;
            CP16(sA + swz64((uint32_t)(r * 64 + cc * 16)), Ap + (size_t)r * K + cc * 8);
        }
        #pragma unroll
        for (int i = 0; i < 2; i++) {          // B: 512 chunks
            int c = tid + i * 256, r = c >> 2, cc = c & 3;
            CP16(sB + swz64((uint32_t)(r * 64 + cc * 16)), Bp + (size_t)r * K + cc * 8);
        }
    };

    load_stage(0, 0); CP_COMMIT();
    load_stage(1, 1); CP_COMMIT();
    load_stage(2, 2); CP_COMMIT();

    for (int kt = 0; kt < KT; kt++) {
        CP_WAIT2();
        __syncthreads();
        uint32_t sA = sbase + (uint32_t)(kt & 3) * STB;
        uint32_t sB = sA + ASTB;
        #pragma unroll
        for (int ks = 0; ks < 2; ks++) {
            const uint32_t kb = ks * 32;       // byte offset of k-step (16 bf16)
            uint32_t a[4][4], b[8][2];
            #pragma unroll
            for (int mi = 0; mi < 4; mi++) {
                uint32_t r = (uint32_t)(wm * 64 + mi * 16 + g) * 64 + kb + q * 4;
                a[mi][0] = lds32(sA + swz64(r));
                a[mi][1] = lds32(sA + swz64(r + 8 * 64));
                a[mi][2] = lds32(sA + swz64(r + 16));
                a[mi][3] = lds32(sA + swz64(r + 8 * 64 + 16));
            }
            #pragma unroll
            for (int ni = 0; ni < 8; ni++) {
                uint32_t r = (uint32_t)(wn * 64 + ni * 8 + g) * 64 + kb + q * 4;
                b[ni][0] = lds32(sB + swz64(r));
                b[ni][1] = lds32(sB + swz64(r + 16));
            }
            #pragma unroll
            for (int mi = 0; mi < 4; mi++)
                #pragma unroll
                for (int ni = 0; ni < 8; ni++)
                    mma_bf16(acc[mi][ni], a[mi], b[ni]);
        }
        if (kt + 3 < KT) load_stage(kt + 3, (kt + 3) & 3);
        CP_COMMIT();
    }

    // ---- epilogue ----
    #pragma unroll
    for (int mi = 0; mi < 4; mi++) {
        int r0 = row0 + wm * 64 + mi * 16 + g;
        #pragma unroll
        for (int ni = 0; ni < 8; ni++) {
            int c = col0 + wn * 64 + ni * 8 + q * 2;
            float b0 = bias[c], b1 = bias[c + 1];
            float v0 = acc[mi][ni][0] + b0;
            float v1 = acc[mi][ni][1] + b1;
            float v2 = acc[mi][ni][2] + b0;
            float v3 = acc[mi][ni][3] + b1;
            if (OT == 1) {
                v0 = 0.5f * v0 * (1.f + erff(v0 * 0.70710678118654752f));
                v1 = 0.5f * v1 * (1.f + erff(v1 * 0.70710678118654752f));
                v2 = 0.5f * v2 * (1.f + erff(v2 * 0.70710678118654752f));
                v3 = 0.5f * v3 * (1.f + erff(v3 * 0.70710678118654752f));
            }
            if (OT == 3) {
                float2 ra = *(const float2*)&res[(size_t)r0 * N + c];
                float2 rb = *(const float2*)&res[(size_t)(r0 + 8) * N + c];
                v0 += ra.x; v1 += ra.y; v2 += rb.x; v3 += rb.y;
            }
            if (OT <= 1) {
                *(__nv_bfloat162*)&((__nv_bfloat16*)Cm)[(size_t)r0 * N + c]       = pack_bf2(v0, v1);
                *(__nv_bfloat162*)&((__nv_bfloat16*)Cm)[(size_t)(r0 + 8) * N + c] = pack_bf2(v2, v3);
            } else {
                *(float2*)&((float*)Cm)[(size_t)r0 * N + c]       = make_float2(v0, v1);
                *(float2*)&((float*)Cm)[(size_t)(r0 + 8) * N + c] = make_float2(v2, v3);
            }
        }
    }
}

// ---------------- block reduce (sum, sumsq) over 128 threads ----------------
__device__ __forceinline__ void blockReduce2(float& s, float& s2) {
    #pragma unroll
    for (int o = 16; o > 0; o >>= 1) {
        s  += __shfl_down_sync(0xFFFFFFFFu, s,  o);
        s2 += __shfl_down_sync(0xFFFFFFFFu, s2, o);
    }
    __shared__ float sh[4][2];
    int w = threadIdx.x >> 5, l = threadIdx.x & 31;
    if (l == 0) { sh[w][0] = s; sh[w][1] = s2; }
    __syncthreads();
    if (threadIdx.x == 0) {
        float a = 0.f, b = 0.f;
        #pragma unroll
        for (int i = 0; i < 4; i++) { a += sh[i][0]; b += sh[i][1]; }
        sh[0][0] = a; sh[0][1] = b;
    }
    __syncthreads();
    s = sh[0][0]; s2 = sh[0][1];
}

// ---------------- LN1 + shift + window partition -> bf16 ----------------
__global__ void k_ln1(const float* __restrict__ x, const float* __restrict__ w,
                      const float* __restrict__ bi, __nv_bfloat16* __restrict__ out) {
    int t = blockIdx.x;
    int widx = t / Ntok, n = t % Ntok;
    int b  = widx / NWim, wi = widx % NWim;
    int wh = wi / 8, ww = wi % 8;
    int r  = wh * WS + n / WS, c = ww * WS + n % WS;
    int sh = (r + SS) % Hh, sw = (c + SS) % Wd;
    const float* src = x + ((size_t)b * (Hh*Wd) + sh * Wd + sw) * Cc;

    int tid = threadIdx.x;
    float vals[3]; float s = 0.f, s2 = 0.f;
    #pragma unroll
    for (int i = 0; i < 3; i++) {
        float v = src[tid + i * 128];
        vals[i] = v; s += v; s2 += v * v;
    }
    blockReduce2(s, s2);
    float mean = s * (1.f / Cc);
    float var  = s2 * (1.f / Cc) - mean * mean;
    float inv  = rsqrtf(var + 1e-5f);
    __nv_bfloat16* dst = out + (size_t)t * Cc;
    #pragma unroll
    for (int i = 0; i < 3; i++) {
        int cI = tid + i * 128;
        dst[cI] = __float2bfloat16_rn((vals[i] - mean) * inv * w[cI] + bi[cI]);
    }
}

// ---------------- fused residual(+reverse+unshift) + LN2 ----------------
__global__ void k_resid_ln2(const float* __restrict__ x, const float* __restrict__ proj,
                            const float* __restrict__ w, const float* __restrict__ bi,
                            float* __restrict__ x2, __nv_bfloat16* __restrict__ hout) {
    int t = blockIdx.x;
    int b = t / (Hh * Wd), p = t % (Hh * Wd);
    int h = p / Wd, ww0 = p % Wd;
    int sh = (h + Hh - SS) % Hh, sw = (ww0 + Wd - SS) % Wd;
    int wh = sh / WS, ww = sw / WS;
    int tok = ((b * 8 + wh) * 8 + ww) * Ntok + (sh % WS) * WS + (sw % WS);
    const float* src1 = x    + (size_t)t   * Cc;
    const float* src2 = proj + (size_t)tok * Cc;

    int tid = threadIdx.x;
    float vals[3]; float s = 0.f, s2 = 0.f;
    #pragma unroll
    for (int i = 0; i < 3; i++) {
        int cI = tid + i * 128;
        float v = src1[cI] + src2[cI];
        vals[i] = v; s += v; s2 += v * v;
    }
    blockReduce2(s, s2);
    float mean = s * (1.f / Cc);
    float var  = s2 * (1.f / Cc) - mean * mean;
    float inv  = rsqrtf(var + 1e-5f);
    float* d1 = x2 + (size_t)t * Cc;
    __nv_bfloat16* d2 = hout + (size_t)t * Cc;
    #pragma unroll
    for (int i = 0; i < 3; i++) {
        int cI = tid + i * 128;
        d1[cI] = vals[i];
        d2[cI] = __float2bfloat16_rn((vals[i] - mean) * inv * w[cI] + bi[cI]);
    }
}

// ---------------- attention (fp32 compute, bf16 io) ----------------
constexpr int SCP = 52;
__global__ __launch_bounds__(128)
void k_attn(const __nv_bfloat16* __restrict__ qkv, const float* __restrict__ rpb,
            __nv_bfloat16* __restrict__ out) {
    int blk  = blockIdx.x;
    int widx = blk / NHd, hh = blk % NHd;
    int wi = widx % NWim;
    int wh = wi / 8, ww = wi % 8;

    __shared__ float sq[Ntok * HD], sk[Ntok * HD], sv[Ntok * HD];
    __shared__ float sc[SCP * SCP];
    __shared__ float sbias[169];
    __shared__ int   reg[Ntok];

    int tid = threadIdx.x;
    // 49 rows x 32 d, 8 bf16 (16B) per chunk -> 196 chunks
    for (int idx = tid; idx < 196; idx += 128) {
        int row = idx >> 2, d8 = (idx & 3) * 8;
        const __nv_bfloat16* base = qkv + (size_t)(widx * Ntok + row) * ThreeC + hh * HD + d8;
        const float sc0 = 0.17677669529663687f;
        uint4 uq = *(const uint4*)(base);
        uint4 uk = *(const uint4*)(base + Cc);
        uint4 uv = *(const uint4*)(base + 2 * Cc);
        const __nv_bfloat162* pq = (const __nv_bfloat162*)&uq;
        const __nv_bfloat162* pk = (const __nv_bfloat162*)&uk;
        const __nv_bfloat162* pv = (const __nv_bfloat162*)&uv;
        #pragma unroll
        for (int j = 0; j < 4; j++) {
            float2 fq = __bfloat1622float2(pq[j]);
            float2 fk = __bfloat1622float2(pk[j]);
            float2 fv = __bfloat1622float2(pv[j]);
            sq[row * HD + d8 + 2*j]     = fq.x * sc0;
            sq[row * HD + d8 + 2*j + 1] = fq.y * sc0;
            sk[row * HD + d8 + 2*j]     = fk.x;
            sk[row * HD + d8 + 2*j + 1] = fk.y;
            sv[row * HD + d8 + 2*j]     = fv.x;
            sv[row * HD + d8 + 2*j + 1] = fv.y;
        }
    }
    if (tid < Ntok) {
        int r = wh * WS + tid / WS, c = ww * WS + tid % WS;
        int hr = (r < Hh - WS) ? 0 : ((r < Hh - SS) ? 1 : 2);
        int wr = (c < Wd - WS) ? 0 : ((c < Wd - SS) ? 1 : 2);
        reg[tid] = hr * 3 + wr;
    }
    for (int idx = tid; idx < 169; idx += 128)
        sbias[idx] = rpb[idx * NHd + hh];
    __syncthreads();

    // QK^T: 13x13 grid of 4x4 tiles
    for (int t = tid; t < 169; t += 128) {
        int i0 = (t / 13) * 4, j0 = (t % 13) * 4;
        float a4[4][4];
        #pragma unroll
        for (int r = 0; r < 4; r++)
            #pragma unroll
            for (int c = 0; c < 4; c++) a4[r][c] = 0.f;
        #pragma unroll
        for (int dv = 0; dv < 8; dv++) {
            float4 qr[4], kr[4];
            #pragma unroll
            for (int r = 0; r < 4; r++) qr[r] = *(const float4*)&sq[(i0 + r) * HD + dv * 4];
            #pragma unroll
            for (int c = 0; c < 4; c++) kr[c] = *(const float4*)&sk[(j0 + c) * HD + dv * 4];
            #pragma unroll
            for (int r = 0; r < 4; r++)
                #pragma unroll
                for (int c = 0; c < 4; c++) {
                    a4[r][c] = fmaf(qr[r].x, kr[c].x, a4[r][c]);
                    a4[r][c] = fmaf(qr[r].y, kr[c].y, a4[r][c]);
                    a4[r][c] = fmaf(qr[r].z, kr[c].z, a4[r][c]);
                    a4[r][c] = fmaf(qr[r].w, kr[c].w, a4[r][c]);
                }
        }
        #pragma unroll
        for (int r = 0; r < 4; r++) {
            int i = i0 + r;
            if (i >= Ntok) break;
            #pragma unroll
            for (int c = 0; c < 4; c++) {
                int j = j0 + c;
                if (j >= Ntok) continue;
                int dr = i / WS - j / WS + (WS - 1);
                int dc = i % WS - j % WS + (WS - 1);
                float v = a4[r][c] + sbias[dr * 13 + dc];
                if (reg[i] != reg[j]) v -= 100.f;
                sc[i * SCP + j] = v;
            }
        }
    }
    __syncthreads();

    if (tid < Ntok) {
        float* row = &sc[tid * SCP];
        float mx = row[48];
        #pragma unroll
        for (int j4 = 0; j4 < 48; j4 += 4) {
            float4 v = *(const float4*)&row[j4];
            mx = fmaxf(mx, fmaxf(fmaxf(v.x, v.y), fmaxf(v.z, v.w)));
        }
        float sum = __expf(row[48] - mx);
        row[48] = sum;
        #pragma unroll
        for (int j4 = 0; j4 < 48; j4 += 4) {
            float4 v = *(const float4*)&row[j4];
            v.x = __expf(v.x - mx); v.y = __expf(v.y - mx);
            v.z = __expf(v.z - mx); v.w = __expf(v.w - mx);
            sum += v.x + v.y + v.z + v.w;
            *(float4*)&row[j4] = v;
        }
        float inv = 1.f / sum;
        row[48] *= inv;
        #pragma unroll
        for (int j4 = 0; j4 < 48; j4 += 4) {
            float4 v = *(const float4*)&row[j4];
            v.x *= inv; v.y *= inv; v.z *= inv; v.w *= inv;
            *(float4*)&row[j4] = v;
        }
    }
    __syncthreads();

    // AV: 13 i-tiles x 8 d-tiles
    if (tid < 104) {
        int i0 = (tid / 8) * 4, d0 = (tid % 8) * 4;
        float a4[4][4];
        #pragma unroll
        for (int r = 0; r < 4; r++)
            #pragma unroll
            for (int c = 0; c < 4; c++) a4[r][c] = 0.f;
        for (int j0 = 0; j0 < 48; j0 += 4) {
            float4 s4[4], v4[4];
            #pragma unroll
            for (int r = 0; r < 4; r++) s4[r] = *(const float4*)&sc[(i0 + r) * SCP + j0];
            #pragma unroll
            for (int c = 0; c < 4; c++) v4[c] = *(const float4*)&sv[(j0 + c) * HD + d0];
            #pragma unroll
            for (int r = 0; r < 4; r++) {
                #pragma unroll
                for (int c = 0; c < 4; c++) {
                    float acc = a4[r][c];
                    acc = fmaf(s4[r].x, (&v4[0].x)[c], acc);
                    acc = fmaf(s4[r].y, (&v4[1].x)[c], acc);
                    acc = fmaf(s4[r].z, (&v4[2].x)[c], acc);
                    acc = fmaf(s4[r].w, (&v4[3].x)[c], acc);
                    a4[r][c] = acc;
                }
            }
        }
        {
            float4 v4 = *(const float4*)&sv[48 * HD + d0];
            #pragma unroll
            for (int r = 0; r < 4; r++) {
                float s = sc[(i0 + r) * SCP + 48];
                a4[r][0] = fmaf(s, v4.x, a4[r][0]);
                a4[r][1] = fmaf(s, v4.y, a4[r][1]);
                a4[r][2] = fmaf(s, v4.z, a4[r][2]);
                a4[r][3] = fmaf(s, v4.w, a4[r][3]);
            }
        }
        #pragma unroll
        for (int r = 0; r < 4; r++) {
            int i = i0 + r;
            if (i >= Ntok) break;
            __nv_bfloat162 o0 = pack_bf2(a4[r][0], a4[r][1]);
            __nv_bfloat162 o1 = pack_bf2(a4[r][2], a4[r][3]);
            __nv_bfloat16* dst = out + (size_t)(widx * Ntok + i) * Cc + hh * HD + d0;
            *(__nv_bfloat162*)(dst)     = o0;
            *(__nv_bfloat162*)(dst + 2) = o1;
        }
    }
}

// ---------------- host launch ----------------
extern "C" void kernel_launch(void* const* d_in, const int* in_sizes, int n_in,
                              void* d_out, int out_size) {
    const float* x      = (const float*)d_in[0];
    const float* n1w    = (const float*)d_in[1];
    const float* n1b    = (const float*)d_in[2];
    const float* qkv_w  = (const float*)d_in[3];
    const float* qkv_b  = (const float*)d_in[4];
    const float* rpb    = (const float*)d_in[5];
    const float* proj_w = (const float*)d_in[6];
    const float* proj_b = (const float*)d_in[7];
    const float* n2w    = (const float*)d_in[8];
    const float* n2b    = (const float*)d_in[9];
    const float* fc1_w  = (const float*)d_in[10];
    const float* fc1_b  = (const float*)d_in[11];
    const float* fc2_w  = (const float*)d_in[12];
    const float* fc2_b  = (const float*)d_in[13];
    float* out = (float*)d_out;

    __nv_bfloat16 *p_xw, *p_qkv, *p_attb, *p_h, *p_f1, *p_wt;
    float *p_proj, *p_x2;
    cudaGetSymbolAddress((void**)&p_xw,   g_xw);
    cudaGetSymbolAddress((void**)&p_qkv,  g_qkv);
    cudaGetSymbolAddress((void**)&p_attb, g_attb);
    cudaGetSymbolAddress((void**)&p_proj, g_proj);
    cudaGetSymbolAddress((void**)&p_x2,   g_x2);
    cudaGetSymbolAddress((void**)&p_h,    g_h);
    cudaGetSymbolAddress((void**)&p_f1,   g_f1);
    cudaGetSymbolAddress((void**)&p_wt,   g_wt);

    cudaFuncSetAttribute(k_gemm_bf<0, __nv_bfloat16>, cudaFuncAttributeMaxDynamicSharedMemorySize, SMEM_GEMM);
    cudaFuncSetAttribute(k_gemm_bf<1, __nv_bfloat16>, cudaFuncAttributeMaxDynamicSharedMemorySize, SMEM_GEMM);
    cudaFuncSetAttribute(k_gemm_bf<2, float>,         cudaFuncAttributeMaxDynamicSharedMemorySize, SMEM_GEMM);
    cudaFuncSetAttribute(k_gemm_bf<3, float>,         cudaFuncAttributeMaxDynamicSharedMemorySize, SMEM_GEMM);

    // 0. transpose + bf16 weights
    k_transpose<<<dim3(ThreeC/32, Cc/32), dim3(32,8)>>>(qkv_w,  p_wt + WT_QKV,  Cc, ThreeC);
    k_transpose<<<dim3(Cc/32,    Cc/32), dim3(32,8)>>>(proj_w, p_wt + WT_PROJ, Cc, Cc);
    k_transpose<<<dim3(MLPH/32,  Cc/32), dim3(32,8)>>>(fc1_w,  p_wt + WT_FC1,  Cc, MLPH);
    k_transpose<<<dim3(Cc/32,  MLPH/32), dim3(32,8)>>>(fc2_w,  p_wt + WT_FC2,  MLPH, Cc);

    // 1. LN1 + shift + window partition
    k_ln1<<<Mrows, 128>>>(x, n1w, n1b, p_xw);

    // 2. QKV GEMM -> bf16
    k_gemm_bf<0, __nv_bfloat16><<<dim3(ThreeC/GBN, Mrows/GBM), 256, SMEM_GEMM>>>(
        p_xw, p_wt + WT_QKV, qkv_b, nullptr, p_qkv, Mrows, ThreeC, Cc);

    // 3. windowed attention -> bf16
    k_attn<<<(Bn * NWim) * NHd, 128>>>(p_qkv, rpb, p_attb);

    // 4. proj GEMM -> f32
    k_gemm_bf<2, float><<<dim3(Cc/GBN, Mrows/GBM), 256, SMEM_GEMM>>>(
        p_attb, p_wt + WT_PROJ, proj_b, nullptr, p_proj, Mrows, Cc, Cc);

    // 5+6. residual + reverse + unshift + LN2
    k_resid_ln2<<<Mrows, 128>>>(x, p_proj, n2w, n2b, p_x2, p_h);

    // 7. fc1 GEMM + GELU -> bf16
    k_gemm_bf<1, __nv_bfloat16><<<dim3(MLPH/GBN, Mrows/GBM), 256, SMEM_GEMM>>>(
        p_h, p_wt + WT_FC1, fc1_b, nullptr, p_f1, Mrows, MLPH, Cc);

    // 8. fc2 GEMM + bias + residual -> f32 out
    k_gemm_bf<3, float><<<dim3(Cc/GBN, Mrows/GBM), 256, SMEM_GEMM>>>(
        p_f1, p_wt + WT_FC2, fc2_b, p_x2, out, Mrows, Cc, MLPH);
}

// round 7
// speedup vs baseline: 5.2531x; 1.0002x over previous
#include <cuda_runtime.h>
#include <cuda_bf16.h>
#include <math.h>
#include <stdint.h>

// ---------------- problem constants ----------------
constexpr int Bn   = 32;
constexpr int Hh   = 56;
constexpr int Wd   = 56;
constexpr int Cc   = 384;
constexpr int NHd  = 12;
constexpr int WS   = 7;
constexpr int SS   = 3;
constexpr int Ntok = WS * WS;            // 49
constexpr int NWim = (Hh/WS) * (Wd/WS);  // 64
constexpr int HD   = Cc / NHd;           // 32
constexpr int MLPH = 4 * Cc;             // 1536
constexpr int Mrows = Bn * Hh * Wd;      // 100352
constexpr int ThreeC = 3 * Cc;           // 1152

// ---------------- scratch (device globals) ----------------
__device__ __nv_bfloat16 g_xw  [(size_t)Mrows * Cc];
__device__ __nv_bfloat16 g_qkv [(size_t)Mrows * ThreeC];
__device__ __nv_bfloat16 g_attb[(size_t)Mrows * Cc];
__device__ float         g_proj[(size_t)Mrows * Cc];
__device__ float         g_x2  [(size_t)Mrows * Cc];
__device__ __nv_bfloat16 g_h   [(size_t)Mrows * Cc];
__device__ __nv_bfloat16 g_f1  [(size_t)Mrows * MLPH];
constexpr size_t WT_QKV  = 0;
constexpr size_t WT_PROJ = WT_QKV  + (size_t)Cc * ThreeC;
constexpr size_t WT_FC1  = WT_PROJ + (size_t)Cc * Cc;
constexpr size_t WT_FC2  = WT_FC1  + (size_t)Cc * MLPH;
__device__ __nv_bfloat16 g_wt[WT_FC2 + (size_t)MLPH * Cc];

// ---------------- helpers ----------------
__device__ __forceinline__ uint32_t smem_u32(const void* p) {
    uint32_t a;
    asm("{ .reg .u64 t; cvta.to.shared.u64 t, %1; cvt.u32.u64 %0, t; }" : "=r"(a) : "l"(p));
    return a;
}
#define CP16(dst, src) asm volatile("cp.async.cg.shared.global [%0], [%1], 16;\n" :: "r"(dst), "l"(src))
#define CP_COMMIT()    asm volatile("cp.async.commit_group;\n" ::: "memory")
#define CP_WAIT2()     asm volatile("cp.async.wait_group 2;\n" ::: "memory")

__device__ __forceinline__ uint32_t swz64(uint32_t off) {
    return off ^ ((off >> 3) & 0x30);
}
__device__ __forceinline__ void ldsm_x4(uint32_t* r, uint32_t addr) {
    asm volatile("ldmatrix.sync.aligned.m8n8.x4.shared.b16 {%0,%1,%2,%3}, [%4];"
        : "=r"(r[0]), "=r"(r[1]), "=r"(r[2]), "=r"(r[3]) : "r"(addr));
}
__device__ __forceinline__ void mma_bf16(float* d, const uint32_t* a,
                                         uint32_t b0, uint32_t b1) {
    asm volatile(
        "mma.sync.aligned.m16n8k16.row.col.f32.bf16.bf16.f32 "
        "{%0,%1,%2,%3}, {%4,%5,%6,%7}, {%8,%9}, {%0,%1,%2,%3};\n"
        : "+f"(d[0]), "+f"(d[1]), "+f"(d[2]), "+f"(d[3])
        : "r"(a[0]), "r"(a[1]), "r"(a[2]), "r"(a[3]), "r"(b0), "r"(b1));
}
__device__ __forceinline__ __nv_bfloat162 pack_bf2(float a, float b) {
    return __floats2bfloat162_rn(a, b);
}

// ---------------- weight transpose + bf16: W[K,N] -> Wt[N,K] ----------------
__global__ void k_transpose(const float* __restrict__ W, __nv_bfloat16* __restrict__ Wt,
                            int K, int N) {
    __shared__ float t[32][33];
    int k0 = blockIdx.y * 32, n0 = blockIdx.x * 32;
    int tx = threadIdx.x, ty = threadIdx.y;
    #pragma unroll
    for (int i = 0; i < 32; i += 8)
        t[ty + i][tx] = W[(size_t)(k0 + ty + i) * N + n0 + tx];
    __syncthreads();
    #pragma unroll
    for (int i = 0; i < 32; i += 8)
        Wt[(size_t)(n0 + ty + i) * K + k0 + tx] = __float2bfloat16_rn(t[tx][ty + i]);
}

// ---------------- bf16 mma.sync GEMM with ldmatrix ----------------
// CTA 256x128, BK=32, 8 warps (4M x 2N), warp tile 64x64.
// smem: 64B rows (32 bf16 = one k-tile), SW64 swizzle. 4-stage cp.async.
// OT: 0 = bias,bf16 ; 1 = bias+gelu,bf16 ; 2 = bias,f32 ; 3 = bias+res,f32
constexpr int GBM = 256, GBN = 128;
constexpr int ASTB = GBM * 64;            // 16384
constexpr int BSTB = GBN * 64;            // 8192
constexpr int STB  = ASTB + BSTB;         // 24576
constexpr int SMEM_GEMM = 4 * STB;        // 98304

template <int OT, typename OutT>
__global__ __launch_bounds__(256, 1)
void k_gemm_bf(const __nv_bfloat16* __restrict__ A, const __nv_bfloat16* __restrict__ Wt,
               const float* __restrict__ bias, const float* __restrict__ res,
               OutT* __restrict__ Cm, int M, int N, int K) {
    extern __shared__ char smem[];
    uint32_t sbase = smem_u32(smem);

    const int tid  = threadIdx.x;
    const int lane = tid & 31, warp = tid >> 5;
    const int wm = warp & 3, wn = warp >> 2;
    const int g = lane >> 2, q = lane & 3;
    const int row0 = blockIdx.y * GBM, col0 = blockIdx.x * GBN;
    const int KT = K / 32;

    const __nv_bfloat16* Ab = A  + (size_t)row0 * K;
    const __nv_bfloat16* Bb = Wt + (size_t)col0 * K;

    // per-thread ldmatrix offsets (stage-relative, ks=0)
    uint32_t a_off[4], b_off[4];
    {
        int rowa = wm * 64 + (lane & 15);
        int sega = lane >> 4;                       // 0/1 -> k 0-7 / 8-15
        #pragma unroll
        for (int mi = 0; mi < 4; mi++)
            a_off[mi] = swz64((uint32_t)(rowa + mi * 16) * 64 + sega * 16);
        int rowb = wn * 64 + (lane & 7) + ((lane >> 4) << 3);
        int segb = (lane >> 3) & 1;
        #pragma unroll
        for (int p = 0; p < 4; p++)
            b_off[p] = ASTB + swz64((uint32_t)(rowb + p * 16) * 64 + segb * 16);
    }

    float acc[4][8][4];
    #pragma unroll
    for (int i = 0; i < 4; i++)
        #pragma unroll
        for (int j = 0; j < 8; j++)
            #pragma unroll
            for (int r = 0; r < 4; r++) acc[i][j][r] = 0.f;

    auto load_stage = [&](int kt, int s) {
        uint32_t sA = sbase + (uint32_t)s * STB;
        uint32_t sB = sA + ASTB;
        const __nv_bfloat16* Ap = Ab + kt * 32;
        const __nv_bfloat16* Bp = Bb + kt * 32;
        #pragma unroll
        for (int i = 0; i < 4; i++) {
            int c = tid + i * 256, r = c >> 2, cc = c & 3;
            CP16(sA + swz64((uint32_t)(r * 64 + cc * 16)), Ap + (size_t)r * K + cc * 8);
        }
        #pragma unroll
        for (int i = 0; i < 2; i++) {
            int c = tid + i * 256, r = c >> 2, cc = c & 3;
            CP16(sB + swz64((uint32_t)(r * 64 + cc * 16)), Bp + (size_t)r * K + cc * 8);
        }
    };

    load_stage(0, 0); CP_COMMIT();
    load_stage(1, 1); CP_COMMIT();
    load_stage(2, 2); CP_COMMIT();

    for (int kt = 0; kt < KT; kt++) {
        CP_WAIT2();
        __syncthreads();
        uint32_t st = sbase + (uint32_t)(kt & 3) * STB;
        #pragma unroll
        for (int ks = 0; ks < 2; ks++) {
            const uint32_t kx = (uint32_t)ks * 0x20;   // +2 logical segs = XOR bit5
            uint32_t a[4][4], b[4][4];
            #pragma unroll
            for (int mi = 0; mi < 4; mi++) ldsm_x4(a[mi], st + (a_off[mi] ^ kx));
            #pragma unroll
            for (int p = 0; p < 4; p++)   ldsm_x4(b[p],  st + (b_off[p]  ^ kx));
            #pragma unroll
            for (int mi = 0; mi < 4; mi++)
                #pragma unroll
                for (int p = 0; p < 4; p++) {
                    mma_bf16(acc[mi][2 * p],     a[mi], b[p][0], b[p][1]);
                    mma_bf16(acc[mi][2 * p + 1], a[mi], b[p][2], b[p][3]);
                }
        }
        if (kt + 3 < KT) load_stage(kt + 3, (kt + 3) & 3);
        CP_COMMIT();
    }

    // ---- epilogue ----
    #pragma unroll
    for (int mi = 0; mi < 4; mi++) {
        int r0 = row0 + wm * 64 + mi * 16 + g;
        #pragma unroll
        for (int ni = 0; ni < 8; ni++) {
            int c = col0 + wn * 64 + ni * 8 + q * 2;
            float b0 = bias[c], b1 = bias[c + 1];
            float v0 = acc[mi][ni][0] + b0;
            float v1 = acc[mi][ni][1] + b1;
            float v2 = acc[mi][ni][2] + b0;
            float v3 = acc[mi][ni][3] + b1;
            if (OT == 1) {
                v0 = 0.5f * v0 * (1.f + erff(v0 * 0.70710678118654752f));
                v1 = 0.5f * v1 * (1.f + erff(v1 * 0.70710678118654752f));
                v2 = 0.5f * v2 * (1.f + erff(v2 * 0.70710678118654752f));
                v3 = 0.5f * v3 * (1.f + erff(v3 * 0.70710678118654752f));
            }
            if (OT == 3) {
                float2 ra = *(const float2*)&res[(size_t)r0 * N + c];
                float2 rb = *(const float2*)&res[(size_t)(r0 + 8) * N + c];
                v0 += ra.x; v1 += ra.y; v2 += rb.x; v3 += rb.y;
            }
            if (OT <= 1) {
                *(__nv_bfloat162*)&((__nv_bfloat16*)Cm)[(size_t)r0 * N + c]       = pack_bf2(v0, v1);
                *(__nv_bfloat162*)&((__nv_bfloat16*)Cm)[(size_t)(r0 + 8) * N + c] = pack_bf2(v2, v3);
            } else {
                *(float2*)&((float*)Cm)[(size_t)r0 * N + c]       = make_float2(v0, v1);
                *(float2*)&((float*)Cm)[(size_t)(r0 + 8) * N + c] = make_float2(v2, v3);
            }
        }
    }
}

// ---------------- block reduce (sum, sumsq) over 128 threads ----------------
__device__ __forceinline__ void blockReduce2(float& s, float& s2) {
    #pragma unroll
    for (int o = 16; o > 0; o >>= 1) {
        s  += __shfl_down_sync(0xFFFFFFFFu, s,  o);
        s2 += __shfl_down_sync(0xFFFFFFFFu, s2, o);
    }
    __shared__ float sh[4][2];
    int w = threadIdx.x >> 5, l = threadIdx.x & 31;
    if (l == 0) { sh[w][0] = s; sh[w][1] = s2; }
    __syncthreads();
    if (threadIdx.x == 0) {
        float a = 0.f, b = 0.f;
        #pragma unroll
        for (int i = 0; i < 4; i++) { a += sh[i][0]; b += sh[i][1]; }
        sh[0][0] = a; sh[0][1] = b;
    }
    __syncthreads();
    s = sh[0][0]; s2 = sh[0][1];
}

// ---------------- LN1 + shift + window partition -> bf16 ----------------
__global__ void k_ln1(const float* __restrict__ x, const float* __restrict__ w,
                      const float* __restrict__ bi, __nv_bfloat16* __restrict__ out) {
    int t = blockIdx.x;
    int widx = t / Ntok, n = t % Ntok;
    int b  = widx / NWim, wi = widx % NWim;
    int wh = wi / 8, ww = wi % 8;
    int r  = wh * WS + n / WS, c = ww * WS + n % WS;
    int sh = (r + SS) % Hh, sw = (c + SS) % Wd;
    const float* src = x + ((size_t)b * (Hh*Wd) + sh * Wd + sw) * Cc;

    int tid = threadIdx.x;
    float vals[3]; float s = 0.f, s2 = 0.f;
    #pragma unroll
    for (int i = 0; i < 3; i++) {
        float v = src[tid + i * 128];
        vals[i] = v; s += v; s2 += v * v;
    }
    blockReduce2(s, s2);
    float mean = s * (1.f / Cc);
    float var  = s2 * (1.f / Cc) - mean * mean;
    float inv  = rsqrtf(var + 1e-5f);
    __nv_bfloat16* dst = out + (size_t)t * Cc;
    #pragma unroll
    for (int i = 0; i < 3; i++) {
        int cI = tid + i * 128;
        dst[cI] = __float2bfloat16_rn((vals[i] - mean) * inv * w[cI] + bi[cI]);
    }
}

// ---------------- fused residual(+reverse+unshift) + LN2 ----------------
__global__ void k_resid_ln2(const float* __restrict__ x, const float* __restrict__ proj,
                            const float* __restrict__ w, const float* __restrict__ bi,
                            float* __restrict__ x2, __nv_bfloat16* __restrict__ hout) {
    int t = blockIdx.x;
    int b = t / (Hh * Wd), p = t % (Hh * Wd);
    int h = p / Wd, ww0 = p % Wd;
    int sh = (h + Hh - SS) % Hh, sw = (ww0 + Wd - SS) % Wd;
    int wh = sh / WS, ww = sw / WS;
    int tok = ((b * 8 + wh) * 8 + ww) * Ntok + (sh % WS) * WS + (sw % WS);
    const float* src1 = x    + (size_t)t   * Cc;
    const float* src2 = proj + (size_t)tok * Cc;

    int tid = threadIdx.x;
    float vals[3]; float s = 0.f, s2 = 0.f;
    #pragma unroll
    for (int i = 0; i < 3; i++) {
        int cI = tid + i * 128;
        float v = src1[cI] + src2[cI];
        vals[i] = v; s += v; s2 += v * v;
    }
    blockReduce2(s, s2);
    float mean = s * (1.f / Cc);
    float var  = s2 * (1.f / Cc) - mean * mean;
    float inv  = rsqrtf(var + 1e-5f);
    float* d1 = x2 + (size_t)t * Cc;
    __nv_bfloat16* d2 = hout + (size_t)t * Cc;
    #pragma unroll
    for (int i = 0; i < 3; i++) {
        int cI = tid + i * 128;
        d1[cI] = vals[i];
        d2[cI] = __float2bfloat16_rn((vals[i] - mean) * inv * w[cI] + bi[cI]);
    }
}

// ---------------- attention (fp32 compute, bf16 io), 192 threads ----------------
constexpr int SCP = 52;
__global__ __launch_bounds__(192)
void k_attn(const __nv_bfloat16* __restrict__ qkv, const float* __restrict__ rpb,
            __nv_bfloat16* __restrict__ out) {
    int blk  = blockIdx.x;
    int widx = blk / NHd, hh = blk % NHd;
    int wi = widx % NWim;
    int wh = wi / 8, ww = wi % 8;

    __shared__ float sq[Ntok * HD], sk[Ntok * HD], sv[Ntok * HD];
    __shared__ float sc[SCP * SCP];
    __shared__ float sbias[169];
    __shared__ int   reg[Ntok];

    int tid = threadIdx.x;
    for (int idx = tid; idx < 196; idx += 192) {
        int row = idx >> 2, d8 = (idx & 3) * 8;
        const __nv_bfloat16* base = qkv + (size_t)(widx * Ntok + row) * ThreeC + hh * HD + d8;
        const float sc0 = 0.17677669529663687f;
        uint4 uq = *(const uint4*)(base);
        uint4 uk = *(const uint4*)(base + Cc);
        uint4 uv = *(const uint4*)(base + 2 * Cc);
        const __nv_bfloat162* pq = (const __nv_bfloat162*)&uq;
        const __nv_bfloat162* pk = (const __nv_bfloat162*)&uk;
        const __nv_bfloat162* pv = (const __nv_bfloat162*)&uv;
        #pragma unroll
        for (int j = 0; j < 4; j++) {
            float2 fq = __bfloat1622float2(pq[j]);
            float2 fk = __bfloat1622float2(pk[j]);
            float2 fv = __bfloat1622float2(pv[j]);
            sq[row * HD + d8 + 2*j]     = fq.x * sc0;
            sq[row * HD + d8 + 2*j + 1] = fq.y * sc0;
            sk[row * HD + d8 + 2*j]     = fk.x;
            sk[row * HD + d8 + 2*j + 1] = fk.y;
            sv[row * HD + d8 + 2*j]     = fv.x;
            sv[row * HD + d8 + 2*j + 1] = fv.y;
        }
    }
    if (tid < Ntok) {
        int r = wh * WS + tid / WS, c = ww * WS + tid % WS;
        int hr = (r < Hh - WS) ? 0 : ((r < Hh - SS) ? 1 : 2);
        int wr = (c < Wd - WS) ? 0 : ((c < Wd - SS) ? 1 : 2);
        reg[tid] = hr * 3 + wr;
    }
    for (int idx = tid; idx < 169; idx += 192)
        sbias[idx] = rpb[idx * NHd + hh];
    __syncthreads();

    // QK^T: 13x13 grid of 4x4 tiles, single pass over 192 threads
    if (tid < 169) {
        int i0 = (tid / 13) * 4, j0 = (tid % 13) * 4;
        float a4[4][4];
        #pragma unroll
        for (int r = 0; r < 4; r++)
            #pragma unroll
            for (int c = 0; c < 4; c++) a4[r][c] = 0.f;
        #pragma unroll
        for (int dv = 0; dv < 8; dv++) {
            float4 qr[4], kr[4];
            #pragma unroll
            for (int r = 0; r < 4; r++) qr[r] = *(const float4*)&sq[(i0 + r) * HD + dv * 4];
            #pragma unroll
            for (int c = 0; c < 4; c++) kr[c] = *(const float4*)&sk[(j0 + c) * HD + dv * 4];
            #pragma unroll
            for (int r = 0; r < 4; r++)
                #pragma unroll
                for (int c = 0; c < 4; c++) {
                    a4[r][c] = fmaf(qr[r].x, kr[c].x, a4[r][c]);
                    a4[r][c] = fmaf(qr[r].y, kr[c].y, a4[r][c]);
                    a4[r][c] = fmaf(qr[r].z, kr[c].z, a4[r][c]);
                    a4[r][c] = fmaf(qr[r].w, kr[c].w, a4[r][c]);
                }
        }
        #pragma unroll
        for (int r = 0; r < 4; r++) {
            int i = i0 + r;
            if (i < Ntok) {
                #pragma unroll
                for (int c = 0; c < 4; c++) {
                    int j = j0 + c;
                    if (j < Ntok) {
                        int dr = i / WS - j / WS + (WS - 1);
                        int dc = i % WS - j % WS + (WS - 1);
                        float v = a4[r][c] + sbias[dr * 13 + dc];
                        if (reg[i] != reg[j]) v -= 100.f;
                        sc[i * SCP + j] = v;
                    }
                }
            }
        }
    }
    __syncthreads();

    if (tid < Ntok) {
        float* row = &sc[tid * SCP];
        float mx = row[48];
        #pragma unroll
        for (int j4 = 0; j4 < 48; j4 += 4) {
            float4 v = *(const float4*)&row[j4];
            mx = fmaxf(mx, fmaxf(fmaxf(v.x, v.y), fmaxf(v.z, v.w)));
        }
        float sum = __expf(row[48] - mx);
        row[48] = sum;
        #pragma unroll
        for (int j4 = 0; j4 < 48; j4 += 4) {
            float4 v = *(const float4*)&row[j4];
            v.x = __expf(v.x - mx); v.y = __expf(v.y - mx);
            v.z = __expf(v.z - mx); v.w = __expf(v.w - mx);
            sum += v.x + v.y + v.z + v.w;
            *(float4*)&row[j4] = v;
        }
        float inv = 1.f / sum;
        row[48] *= inv;
        #pragma unroll
        for (int j4 = 0; j4 < 48; j4 += 4) {
            float4 v = *(const float4*)&row[j4];
            v.x *= inv; v.y *= inv; v.z *= inv; v.w *= inv;
            *(float4*)&row[j4] = v;
        }
    }
    __syncthreads();

    // AV: 13 i-tiles x 8 d-tiles = 104 tiles of 4x4
    if (tid < 104) {
        int i0 = (tid / 8) * 4, d0 = (tid % 8) * 4;
        float a4[4][4];
        #pragma unroll
        for (int r = 0; r < 4; r++)
            #pragma unroll
            for (int c = 0; c < 4; c++) a4[r][c] = 0.f;
        for (int j0 = 0; j0 < 48; j0 += 4) {
            float4 s4[4], v4[4];
            #pragma unroll
            for (int r = 0; r < 4; r++) s4[r] = *(const float4*)&sc[(i0 + r) * SCP + j0];
            #pragma unroll
            for (int c = 0; c < 4; c++) v4[c] = *(const float4*)&sv[(j0 + c) * HD + d0];
            #pragma unroll
            for (int r = 0; r < 4; r++) {
                #pragma unroll
                for (int c = 0; c < 4; c++) {
                    float acc = a4[r][c];
                    acc = fmaf(s4[r].x, (&v4[0].x)[c], acc);
                    acc = fmaf(s4[r].y, (&v4[1].x)[c], acc);
                    acc = fmaf(s4[r].z, (&v4[2].x)[c], acc);
                    acc = fmaf(s4[r].w, (&v4[3].x)[c], acc);
                    a4[r][c] = acc;
                }
            }
        }
        {
            float4 v4 = *(const float4*)&sv[48 * HD + d0];
            #pragma unroll
            for (int r = 0; r < 4; r++) {
                float s = sc[(i0 + r) * SCP + 48];
                a4[r][0] = fmaf(s, v4.x, a4[r][0]);
                a4[r][1] = fmaf(s, v4.y, a4[r][1]);
                a4[r][2] = fmaf(s, v4.z, a4[r][2]);
                a4[r][3] = fmaf(s, v4.w, a4[r][3]);
            }
        }
        #pragma unroll
        for (int r = 0; r < 4; r++) {
            int i = i0 + r;
            if (i >= Ntok) break;
            __nv_bfloat162 o0 = pack_bf2(a4[r][0], a4[r][1]);
            __nv_bfloat162 o1 = pack_bf2(a4[r][2], a4[r][3]);
            __nv_bfloat16* dst = out + (size_t)(widx * Ntok + i) * Cc + hh * HD + d0;
            *(__nv_bfloat162*)(dst)     = o0;
            *(__nv_bfloat162*)(dst + 2) = o1;
        }
    }
}

// ---------------- host launch ----------------
extern "C" void kernel_launch(void* const* d_in, const int* in_sizes, int n_in,
                              void* d_out, int out_size) {
    const float* x      = (const float*)d_in[0];
    const float* n1w    = (const float*)d_in[1];
    const float* n1b    = (const float*)d_in[2];
    const float* qkv_w  = (const float*)d_in[3];
    const float* qkv_b  = (const float*)d_in[4];
    const float* rpb    = (const float*)d_in[5];
    const float* proj_w = (const float*)d_in[6];
    const float* proj_b = (const float*)d_in[7];
    const float* n2w    = (const float*)d_in[8];
    const float* n2b    = (const float*)d_in[9];
    const float* fc1_w  = (const float*)d_in[10];
    const float* fc1_b  = (const float*)d_in[11];
    const float* fc2_w  = (const float*)d_in[12];
    const float* fc2_b  = (const float*)d_in[13];
    float* out = (float*)d_out;

    __nv_bfloat16 *p_xw, *p_qkv, *p_attb, *p_h, *p_f1, *p_wt;
    float *p_proj, *p_x2;
    cudaGetSymbolAddress((void**)&p_xw,   g_xw);
    cudaGetSymbolAddress((void**)&p_qkv,  g_qkv);
    cudaGetSymbolAddress((void**)&p_attb, g_attb);
    cudaGetSymbolAddress((void**)&p_proj, g_proj);
    cudaGetSymbolAddress((void**)&p_x2,   g_x2);
    cudaGetSymbolAddress((void**)&p_h,    g_h);
    cudaGetSymbolAddress((void**)&p_f1,   g_f1);
    cudaGetSymbolAddress((void**)&p_wt,   g_wt);

    cudaFuncSetAttribute(k_gemm_bf<0, __nv_bfloat16>, cudaFuncAttributeMaxDynamicSharedMemorySize, SMEM_GEMM);
    cudaFuncSetAttribute(k_gemm_bf<1, __nv_bfloat16>, cudaFuncAttributeMaxDynamicSharedMemorySize, SMEM_GEMM);
    cudaFuncSetAttribute(k_gemm_bf<2, float>,         cudaFuncAttributeMaxDynamicSharedMemorySize, SMEM_GEMM);
    cudaFuncSetAttribute(k_gemm_bf<3, float>,         cudaFuncAttributeMaxDynamicSharedMemorySize, SMEM_GEMM);

    // 0. transpose + bf16 weights
    k_transpose<<<dim3(ThreeC/32, Cc/32), dim3(32,8)>>>(qkv_w,  p_wt + WT_QKV,  Cc, ThreeC);
    k_transpose<<<dim3(Cc/32,    Cc/32), dim3(32,8)>>>(proj_w, p_wt + WT_PROJ, Cc, Cc);
    k_transpose<<<dim3(MLPH/32,  Cc/32), dim3(32,8)>>>(fc1_w,  p_wt + WT_FC1,  Cc, MLPH);
    k_transpose<<<dim3(Cc/32,  MLPH/32), dim3(32,8)>>>(fc2_w,  p_wt + WT_FC2,  MLPH, Cc);

    // 1. LN1 + shift + window partition
    k_ln1<<<Mrows, 128>>>(x, n1w, n1b, p_xw);

    // 2. QKV GEMM -> bf16
    k_gemm_bf<0, __nv_bfloat16><<<dim3(ThreeC/GBN, Mrows/GBM), 256, SMEM_GEMM>>>(
        p_xw, p_wt + WT_QKV, qkv_b, nullptr, p_qkv, Mrows, ThreeC, Cc);

    // 3. windowed attention -> bf16
    k_attn<<<(Bn * NWim) * NHd, 192>>>(p_qkv, rpb, p_attb);

    // 4. proj GEMM -> f32
    k_gemm_bf<2, float><<<dim3(Cc/GBN, Mrows/GBM), 256, SMEM_GEMM>>>(
        p_attb, p_wt + WT_PROJ, proj_b, nullptr, p_proj, Mrows, Cc, Cc);

    // 5+6. residual + reverse + unshift + LN2
    k_resid_ln2<<<Mrows, 128>>>(x, p_proj, n2w, n2b, p_x2, p_h);

    // 7. fc1 GEMM + GELU -> bf16
    k_gemm_bf<1, __nv_bfloat16><<<dim3(MLPH/GBN, Mrows/GBM), 256, SMEM_GEMM>>>(
        p_h, p_wt + WT_FC1, fc1_b, nullptr, p_f1, Mrows, MLPH, Cc);

    // 8. fc2 GEMM + bias + residual -> f32 out
    k_gemm_bf<3, float><<<dim3(Cc/GBN, Mrows/GBM), 256, SMEM_GEMM>>>(
        p_f1, p_wt + WT_FC2, fc2_b, p_x2, out, Mrows, Cc, MLPH);
}

// round 8
// speedup vs baseline: 5.4025x; 1.0284x over previous
#include <cuda_runtime.h>
#include <cuda_bf16.h>
#include <math.h>
#include <stdint.h>

// ---------------- problem constants ----------------
constexpr int Bn   = 32;
constexpr int Hh   = 56;
constexpr int Wd   = 56;
constexpr int Cc   = 384;
constexpr int NHd  = 12;
constexpr int WS   = 7;
constexpr int SS   = 3;
constexpr int Ntok = WS * WS;            // 49
constexpr int NWim = (Hh/WS) * (Wd/WS);  // 64
constexpr int HD   = Cc / NHd;           // 32
constexpr int MLPH = 4 * Cc;             // 1536
constexpr int Mrows = Bn * Hh * Wd;      // 100352
constexpr int ThreeC = 3 * Cc;           // 1152

// ---------------- scratch (device globals) ----------------
__device__ __nv_bfloat16 g_xw  [(size_t)Mrows * Cc];
__device__ __nv_bfloat16 g_qkv [(size_t)Mrows * ThreeC];
__device__ __nv_bfloat16 g_attb[(size_t)Mrows * Cc];
__device__ float         g_proj[(size_t)Mrows * Cc];
__device__ float         g_x2  [(size_t)Mrows * Cc];
__device__ __nv_bfloat16 g_h   [(size_t)Mrows * Cc];
__device__ __nv_bfloat16 g_f1  [(size_t)Mrows * MLPH];
constexpr size_t WT_QKV  = 0;
constexpr size_t WT_PROJ = WT_QKV  + (size_t)Cc * ThreeC;
constexpr size_t WT_FC1  = WT_PROJ + (size_t)Cc * Cc;
constexpr size_t WT_FC2  = WT_FC1  + (size_t)Cc * MLPH;
__device__ __nv_bfloat16 g_wt[WT_FC2 + (size_t)MLPH * Cc];

// ---------------- helpers ----------------
__device__ __forceinline__ uint32_t smem_u32(const void* p) {
    uint32_t a;
    asm("{ .reg .u64 t; cvta.to.shared.u64 t, %1; cvt.u32.u64 %0, t; }" : "=r"(a) : "l"(p));
    return a;
}
#define CP16(dst, src) asm volatile("cp.async.cg.shared.global [%0], [%1], 16;\n" :: "r"(dst), "l"(src))
#define CP_COMMIT()    asm volatile("cp.async.commit_group;\n" ::: "memory")
#define CP_WAIT2()     asm volatile("cp.async.wait_group 2;\n" ::: "memory")

__device__ __forceinline__ uint32_t swz64(uint32_t off) {
    return off ^ ((off >> 3) & 0x30);
}
__device__ __forceinline__ void ldsm_x4(uint32_t* r, uint32_t addr) {
    asm volatile("ldmatrix.sync.aligned.m8n8.x4.shared.b16 {%0,%1,%2,%3}, [%4];"
        : "=r"(r[0]), "=r"(r[1]), "=r"(r[2]), "=r"(r[3]) : "r"(addr));
}
__device__ __forceinline__ void mma_bf16(float* d, const uint32_t* a,
                                         uint32_t b0, uint32_t b1) {
    asm volatile(
        "mma.sync.aligned.m16n8k16.row.col.f32.bf16.bf16.f32 "
        "{%0,%1,%2,%3}, {%4,%5,%6,%7}, {%8,%9}, {%0,%1,%2,%3};\n"
        : "+f"(d[0]), "+f"(d[1]), "+f"(d[2]), "+f"(d[3])
        : "r"(a[0]), "r"(a[1]), "r"(a[2]), "r"(a[3]), "r"(b0), "r"(b1));
}
__device__ __forceinline__ __nv_bfloat162 pack_bf2(float a, float b) {
    return __floats2bfloat162_rn(a, b);
}

// ---------------- single-launch weight transpose + bf16: W[K,N] -> Wt[N,K] ------
// blocks 0..431: qkv (36x12) | 432..575: proj (12x12) | 576..1151: fc1 (48x12)
// | 1152..1727: fc2 (12x48)
__global__ void k_transpose_all(const float* __restrict__ qkv_w, const float* __restrict__ proj_w,
                                const float* __restrict__ fc1_w, const float* __restrict__ fc2_w,
                                __nv_bfloat16* __restrict__ wt) {
    int t = blockIdx.x;
    const float* W; __nv_bfloat16* Wt; int K, N, tile, ntx;
    if (t < 432)       { W = qkv_w;  Wt = wt + WT_QKV;  K = Cc;   N = ThreeC; tile = t;        ntx = 36; }
    else if (t < 576)  { W = proj_w; Wt = wt + WT_PROJ; K = Cc;   N = Cc;     tile = t - 432;  ntx = 12; }
    else if (t < 1152) { W = fc1_w;  Wt = wt + WT_FC1;  K = Cc;   N = MLPH;   tile = t - 576;  ntx = 48; }
    else               { W = fc2_w;  Wt = wt + WT_FC2;  K = MLPH; N = Cc;     tile = t - 1152; ntx = 12; }
    int n0 = (tile % ntx) * 32, k0 = (tile / ntx) * 32;

    __shared__ float sm[32][33];
    int tx = threadIdx.x, ty = threadIdx.y;
    #pragma unroll
    for (int i = 0; i < 32; i += 8)
        sm[ty + i][tx] = W[(size_t)(k0 + ty + i) * N + n0 + tx];
    __syncthreads();
    #pragma unroll
    for (int i = 0; i < 32; i += 8)
        Wt[(size_t)(n0 + ty + i) * K + k0 + tx] = __float2bfloat16_rn(sm[tx][ty + i]);
}

// ---------------- bf16 mma.sync GEMM, 512 threads (16 warps) ----------------
// CTA 256x128, BK=32, 16 warps (8M x 2N), warp tile 32x64.
// smem: 64B rows, SW64 swizzle. 4-stage cp.async.
// OT: 0 = bias,bf16 ; 1 = bias+gelu,bf16 ; 2 = bias,f32 ; 3 = bias+res,f32
constexpr int GBM = 256, GBN = 128;
constexpr int ASTB = GBM * 64;            // 16384
constexpr int BSTB = GBN * 64;            // 8192
constexpr int STB  = ASTB + BSTB;         // 24576
constexpr int SMEM_GEMM = 4 * STB;        // 98304

template <int OT, typename OutT>
__global__ __launch_bounds__(512, 1)
void k_gemm_bf(const __nv_bfloat16* __restrict__ A, const __nv_bfloat16* __restrict__ Wt,
               const float* __restrict__ bias, const float* __restrict__ res,
               OutT* __restrict__ Cm, int M, int N, int K) {
    extern __shared__ char smem[];
    uint32_t sbase = smem_u32(smem);

    const int tid  = threadIdx.x;
    const int lane = tid & 31, warp = tid >> 5;
    const int wm = warp >> 1, wn = warp & 1;      // 8 M-warps x 2 N-warps
    const int g = lane >> 2, q = lane & 3;
    const int row0 = blockIdx.y * GBM, col0 = blockIdx.x * GBN;
    const int KT = K / 32;

    const __nv_bfloat16* Ab = A  + (size_t)row0 * K;
    const __nv_bfloat16* Bb = Wt + (size_t)col0 * K;

    // per-thread ldmatrix offsets (stage-relative, ks=0)
    uint32_t a_off[2], b_off[4];
    {
        int rowa = wm * 32 + (lane & 15);
        int sega = lane >> 4;
        #pragma unroll
        for (int mi = 0; mi < 2; mi++)
            a_off[mi] = swz64((uint32_t)(rowa + mi * 16) * 64 + sega * 16);
        int rowb = wn * 64 + (lane & 7) + ((lane >> 4) << 3);
        int segb = (lane >> 3) & 1;
        #pragma unroll
        for (int p = 0; p < 4; p++)
            b_off[p] = ASTB + swz64((uint32_t)(rowb + p * 16) * 64 + segb * 16);
    }

    float acc[2][8][4];
    #pragma unroll
    for (int i = 0; i < 2; i++)
        #pragma unroll
        for (int j = 0; j < 8; j++)
            #pragma unroll
            for (int r = 0; r < 4; r++) acc[i][j][r] = 0.f;

    auto load_stage = [&](int kt, int s) {
        uint32_t sA = sbase + (uint32_t)s * STB;
        uint32_t sB = sA + ASTB;
        const __nv_bfloat16* Ap = Ab + kt * 32;
        const __nv_bfloat16* Bp = Bb + kt * 32;
        #pragma unroll
        for (int i = 0; i < 2; i++) {          // A: 1024 chunks / 512 thr
            int c = tid + i * 512, r = c >> 2, cc = c & 3;
            CP16(sA + swz64((uint32_t)(r * 64 + cc * 16)), Ap + (size_t)r * K + cc * 8);
        }
        {                                       // B: 512 chunks
            int r = tid >> 2, cc = tid & 3;
            CP16(sB + swz64((uint32_t)(r * 64 + cc * 16)), Bp + (size_t)r * K + cc * 8);
        }
    };

    load_stage(0, 0); CP_COMMIT();
    load_stage(1, 1); CP_COMMIT();
    load_stage(2, 2); CP_COMMIT();

    for (int kt = 0; kt < KT; kt++) {
        CP_WAIT2();
        __syncthreads();
        uint32_t st = sbase + (uint32_t)(kt & 3) * STB;
        #pragma unroll
        for (int ks = 0; ks < 2; ks++) {
            const uint32_t kx = (uint32_t)ks * 0x20;
            uint32_t a[2][4], b[4][4];
            #pragma unroll
            for (int mi = 0; mi < 2; mi++) ldsm_x4(a[mi], st + (a_off[mi] ^ kx));
            #pragma unroll
            for (int p = 0; p < 4; p++)    ldsm_x4(b[p],  st + (b_off[p]  ^ kx));
            #pragma unroll
            for (int mi = 0; mi < 2; mi++)
                #pragma unroll
                for (int p = 0; p < 4; p++) {
                    mma_bf16(acc[mi][2 * p],     a[mi], b[p][0], b[p][1]);
                    mma_bf16(acc[mi][2 * p + 1], a[mi], b[p][2], b[p][3]);
                }
        }
        if (kt + 3 < KT) load_stage(kt + 3, (kt + 3) & 3);
        CP_COMMIT();
    }

    // ---- epilogue ----
    #pragma unroll
    for (int mi = 0; mi < 2; mi++) {
        int r0 = row0 + wm * 32 + mi * 16 + g;
        #pragma unroll
        for (int ni = 0; ni < 8; ni++) {
            int c = col0 + wn * 64 + ni * 8 + q * 2;
            float b0 = bias[c], b1 = bias[c + 1];
            float v0 = acc[mi][ni][0] + b0;
            float v1 = acc[mi][ni][1] + b1;
            float v2 = acc[mi][ni][2] + b0;
            float v3 = acc[mi][ni][3] + b1;
            if (OT == 1) {
                v0 = 0.5f * v0 * (1.f + erff(v0 * 0.70710678118654752f));
                v1 = 0.5f * v1 * (1.f + erff(v1 * 0.70710678118654752f));
                v2 = 0.5f * v2 * (1.f + erff(v2 * 0.70710678118654752f));
                v3 = 0.5f * v3 * (1.f + erff(v3 * 0.70710678118654752f));
            }
            if (OT == 3) {
                float2 ra = *(const float2*)&res[(size_t)r0 * N + c];
                float2 rb = *(const float2*)&res[(size_t)(r0 + 8) * N + c];
                v0 += ra.x; v1 += ra.y; v2 += rb.x; v3 += rb.y;
            }
            if (OT <= 1) {
                *(__nv_bfloat162*)&((__nv_bfloat16*)Cm)[(size_t)r0 * N + c]       = pack_bf2(v0, v1);
                *(__nv_bfloat162*)&((__nv_bfloat16*)Cm)[(size_t)(r0 + 8) * N + c] = pack_bf2(v2, v3);
            } else {
                *(float2*)&((float*)Cm)[(size_t)r0 * N + c]       = make_float2(v0, v1);
                *(float2*)&((float*)Cm)[(size_t)(r0 + 8) * N + c] = make_float2(v2, v3);
            }
        }
    }
}

// ---------------- block reduce (sum, sumsq) over 128 threads ----------------
__device__ __forceinline__ void blockReduce2(float& s, float& s2) {
    #pragma unroll
    for (int o = 16; o > 0; o >>= 1) {
        s  += __shfl_down_sync(0xFFFFFFFFu, s,  o);
        s2 += __shfl_down_sync(0xFFFFFFFFu, s2, o);
    }
    __shared__ float sh[4][2];
    int w = threadIdx.x >> 5, l = threadIdx.x & 31;
    if (l == 0) { sh[w][0] = s; sh[w][1] = s2; }
    __syncthreads();
    if (threadIdx.x == 0) {
        float a = 0.f, b = 0.f;
        #pragma unroll
        for (int i = 0; i < 4; i++) { a += sh[i][0]; b += sh[i][1]; }
        sh[0][0] = a; sh[0][1] = b;
    }
    __syncthreads();
    s = sh[0][0]; s2 = sh[0][1];
}

// ---------------- LN1 + shift + window partition -> bf16 ----------------
__global__ void k_ln1(const float* __restrict__ x, const float* __restrict__ w,
                      const float* __restrict__ bi, __nv_bfloat16* __restrict__ out) {
    int t = blockIdx.x;
    int widx = t / Ntok, n = t % Ntok;
    int b  = widx / NWim, wi = widx % NWim;
    int wh = wi / 8, ww = wi % 8;
    int r  = wh * WS + n / WS, c = ww * WS + n % WS;
    int sh = (r + SS) % Hh, sw = (c + SS) % Wd;
    const float* src = x + ((size_t)b * (Hh*Wd) + sh * Wd + sw) * Cc;

    int tid = threadIdx.x;
    float vals[3]; float s = 0.f, s2 = 0.f;
    #pragma unroll
    for (int i = 0; i < 3; i++) {
        float v = src[tid + i * 128];
        vals[i] = v; s += v; s2 += v * v;
    }
    blockReduce2(s, s2);
    float mean = s * (1.f / Cc);
    float var  = s2 * (1.f / Cc) - mean * mean;
    float inv  = rsqrtf(var + 1e-5f);
    __nv_bfloat16* dst = out + (size_t)t * Cc;
    #pragma unroll
    for (int i = 0; i < 3; i++) {
        int cI = tid + i * 128;
        dst[cI] = __float2bfloat16_rn((vals[i] - mean) * inv * w[cI] + bi[cI]);
    }
}

// ---------------- fused residual(+reverse+unshift) + LN2 ----------------
__global__ void k_resid_ln2(const float* __restrict__ x, const float* __restrict__ proj,
                            const float* __restrict__ w, const float* __restrict__ bi,
                            float* __restrict__ x2, __nv_bfloat16* __restrict__ hout) {
    int t = blockIdx.x;
    int b = t / (Hh * Wd), p = t % (Hh * Wd);
    int h = p / Wd, ww0 = p % Wd;
    int sh = (h + Hh - SS) % Hh, sw = (ww0 + Wd - SS) % Wd;
    int wh = sh / WS, ww = sw / WS;
    int tok = ((b * 8 + wh) * 8 + ww) * Ntok + (sh % WS) * WS + (sw % WS);
    const float* src1 = x    + (size_t)t   * Cc;
    const float* src2 = proj + (size_t)tok * Cc;

    int tid = threadIdx.x;
    float vals[3]; float s = 0.f, s2 = 0.f;
    #pragma unroll
    for (int i = 0; i < 3; i++) {
        int cI = tid + i * 128;
        float v = src1[cI] + src2[cI];
        vals[i] = v; s += v; s2 += v * v;
    }
    blockReduce2(s, s2);
    float mean = s * (1.f / Cc);
    float var  = s2 * (1.f / Cc) - mean * mean;
    float inv  = rsqrtf(var + 1e-5f);
    float* d1 = x2 + (size_t)t * Cc;
    __nv_bfloat16* d2 = hout + (size_t)t * Cc;
    #pragma unroll
    for (int i = 0; i < 3; i++) {
        int cI = tid + i * 128;
        d1[cI] = vals[i];
        d2[cI] = __float2bfloat16_rn((vals[i] - mean) * inv * w[cI] + bi[cI]);
    }
}

// ---------------- attention (fp32 compute, bf16 io), 192 threads ----------------
constexpr int SCP = 52;
__global__ __launch_bounds__(192)
void k_attn(const __nv_bfloat16* __restrict__ qkv, const float* __restrict__ rpb,
            __nv_bfloat16* __restrict__ out) {
    int blk  = blockIdx.x;
    int widx = blk / NHd, hh = blk % NHd;
    int wi = widx % NWim;
    int wh = wi / 8, ww = wi % 8;

    __shared__ float sq[Ntok * HD], sk[Ntok * HD], sv[Ntok * HD];
    __shared__ float sc[SCP * SCP];
    __shared__ float sbias[169];
    __shared__ int   reg[Ntok];

    int tid = threadIdx.x;
    for (int idx = tid; idx < 196; idx += 192) {
        int row = idx >> 2, d8 = (idx & 3) * 8;
        const __nv_bfloat16* base = qkv + (size_t)(widx * Ntok + row) * ThreeC + hh * HD + d8;
        const float sc0 = 0.17677669529663687f;
        uint4 uq = *(const uint4*)(base);
        uint4 uk = *(const uint4*)(base + Cc);
        uint4 uv = *(const uint4*)(base + 2 * Cc);
        const __nv_bfloat162* pq = (const __nv_bfloat162*)&uq;
        const __nv_bfloat162* pk = (const __nv_bfloat162*)&uk;
        const __nv_bfloat162* pv = (const __nv_bfloat162*)&uv;
        #pragma unroll
        for (int j = 0; j < 4; j++) {
            float2 fq = __bfloat1622float2(pq[j]);
            float2 fk = __bfloat1622float2(pk[j]);
            float2 fv = __bfloat1622float2(pv[j]);
            sq[row * HD + d8 + 2*j]     = fq.x * sc0;
            sq[row * HD + d8 + 2*j + 1] = fq.y * sc0;
            sk[row * HD + d8 + 2*j]     = fk.x;
            sk[row * HD + d8 + 2*j + 1] = fk.y;
            sv[row * HD + d8 + 2*j]     = fv.x;
            sv[row * HD + d8 + 2*j + 1] = fv.y;
        }
    }
    if (tid < Ntok) {
        int r = wh * WS + tid / WS, c = ww * WS + tid % WS;
        int hr = (r < Hh - WS) ? 0 : ((r < Hh - SS) ? 1 : 2);
        int wr = (c < Wd - WS) ? 0 : ((c < Wd - SS) ? 1 : 2);
        reg[tid] = hr * 3 + wr;
    }
    for (int idx = tid; idx < 169; idx += 192)
        sbias[idx] = rpb[idx * NHd + hh];
    __syncthreads();

    if (tid < 169) {
        int i0 = (tid / 13) * 4, j0 = (tid % 13) * 4;
        float a4[4][4];
        #pragma unroll
        for (int r = 0; r < 4; r++)
            #pragma unroll
            for (int c = 0; c < 4; c++) a4[r][c] = 0.f;
        #pragma unroll
        for (int dv = 0; dv < 8; dv++) {
            float4 qr[4], kr[4];
            #pragma unroll
            for (int r = 0; r < 4; r++) qr[r] = *(const float4*)&sq[(i0 + r) * HD + dv * 4];
            #pragma unroll
            for (int c = 0; c < 4; c++) kr[c] = *(const float4*)&sk[(j0 + c) * HD + dv * 4];
            #pragma unroll
            for (int r = 0; r < 4; r++)
                #pragma unroll
                for (int c = 0; c < 4; c++) {
                    a4[r][c] = fmaf(qr[r].x, kr[c].x, a4[r][c]);
                    a4[r][c] = fmaf(qr[r].y, kr[c].y, a4[r][c]);
                    a4[r][c] = fmaf(qr[r].z, kr[c].z, a4[r][c]);
                    a4[r][c] = fmaf(qr[r].w, kr[c].w, a4[r][c]);
                }
        }
        #pragma unroll
        for (int r = 0; r < 4; r++) {
            int i = i0 + r;
            if (i < Ntok) {
                #pragma unroll
                for (int c = 0; c < 4; c++) {
                    int j = j0 + c;
                    if (j < Ntok) {
                        int dr = i / WS - j / WS + (WS - 1);
                        int dc = i % WS - j % WS + (WS - 1);
                        float v = a4[r][c] + sbias[dr * 13 + dc];
                        if (reg[i] != reg[j]) v -= 100.f;
                        sc[i * SCP + j] = v;
                    }
                }
            }
        }
    }
    __syncthreads();

    if (tid < Ntok) {
        float* row = &sc[tid * SCP];
        float mx = row[48];
        #pragma unroll
        for (int j4 = 0; j4 < 48; j4 += 4) {
            float4 v = *(const float4*)&row[j4];
            mx = fmaxf(mx, fmaxf(fmaxf(v.x, v.y), fmaxf(v.z, v.w)));
        }
        float sum = __expf(row[48] - mx);
        row[48] = sum;
        #pragma unroll
        for (int j4 = 0; j4 < 48; j4 += 4) {
            float4 v = *(const float4*)&row[j4];
            v.x = __expf(v.x - mx); v.y = __expf(v.y - mx);
            v.z = __expf(v.z - mx); v.w = __expf(v.w - mx);
            sum += v.x + v.y + v.z + v.w;
            *(float4*)&row[j4] = v;
        }
        float inv = 1.f / sum;
        row[48] *= inv;
        #pragma unroll
        for (int j4 = 0; j4 < 48; j4 += 4) {
            float4 v = *(const float4*)&row[j4];
            v.x *= inv; v.y *= inv; v.z *= inv; v.w *= inv;
            *(float4*)&row[j4] = v;
        }
    }
    __syncthreads();

    if (tid < 104) {
        int i0 = (tid / 8) * 4, d0 = (tid % 8) * 4;
        float a4[4][4];
        #pragma unroll
        for (int r = 0; r < 4; r++)
            #pragma unroll
            for (int c = 0; c < 4; c++) a4[r][c] = 0.f;
        for (int j0 = 0; j0 < 48; j0 += 4) {
            float4 s4[4], v4[4];
            #pragma unroll
            for (int r = 0; r < 4; r++) s4[r] = *(const float4*)&sc[(i0 + r) * SCP + j0];
            #pragma unroll
            for (int c = 0; c < 4; c++) v4[c] = *(const float4*)&sv[(j0 + c) * HD + d0];
            #pragma unroll
            for (int r = 0; r < 4; r++) {
                #pragma unroll
                for (int c = 0; c < 4; c++) {
                    float acc = a4[r][c];
                    acc = fmaf(s4[r].x, (&v4[0].x)[c], acc);
                    acc = fmaf(s4[r].y, (&v4[1].x)[c], acc);
                    acc = fmaf(s4[r].z, (&v4[2].x)[c], acc);
                    acc = fmaf(s4[r].w, (&v4[3].x)[c], acc);
                    a4[r][c] = acc;
                }
            }
        }
        {
            float4 v4 = *(const float4*)&sv[48 * HD + d0];
            #pragma unroll
            for (int r = 0; r < 4; r++) {
                float s = sc[(i0 + r) * SCP + 48];
                a4[r][0] = fmaf(s, v4.x, a4[r][0]);
                a4[r][1] = fmaf(s, v4.y, a4[r][1]);
                a4[r][2] = fmaf(s, v4.z, a4[r][2]);
                a4[r][3] = fmaf(s, v4.w, a4[r][3]);
            }
        }
        #pragma unroll
        for (int r = 0; r < 4; r++) {
            int i = i0 + r;
            if (i >= Ntok) break;
            __nv_bfloat162 o0 = pack_bf2(a4[r][0], a4[r][1]);
            __nv_bfloat162 o1 = pack_bf2(a4[r][2], a4[r][3]);
            __nv_bfloat16* dst = out + (size_t)(widx * Ntok + i) * Cc + hh * HD + d0;
            *(__nv_bfloat162*)(dst)     = o0;
            *(__nv_bfloat162*)(dst + 2) = o1;
        }
    }
}

// ---------------- host launch ----------------
extern "C" void kernel_launch(void* const* d_in, const int* in_sizes, int n_in,
                              void* d_out, int out_size) {
    const float* x      = (const float*)d_in[0];
    const float* n1w    = (const float*)d_in[1];
    const float* n1b    = (const float*)d_in[2];
    const float* qkv_w  = (const float*)d_in[3];
    const float* qkv_b  = (const float*)d_in[4];
    const float* rpb    = (const float*)d_in[5];
    const float* proj_w = (const float*)d_in[6];
    const float* proj_b = (const float*)d_in[7];
    const float* n2w    = (const float*)d_in[8];
    const float* n2b    = (const float*)d_in[9];
    const float* fc1_w  = (const float*)d_in[10];
    const float* fc1_b  = (const float*)d_in[11];
    const float* fc2_w  = (const float*)d_in[12];
    const float* fc2_b  = (const float*)d_in[13];
    float* out = (float*)d_out;

    __nv_bfloat16 *p_xw, *p_qkv, *p_attb, *p_h, *p_f1, *p_wt;
    float *p_proj, *p_x2;
    cudaGetSymbolAddress((void**)&p_xw,   g_xw);
    cudaGetSymbolAddress((void**)&p_qkv,  g_qkv);
    cudaGetSymbolAddress((void**)&p_attb, g_attb);
    cudaGetSymbolAddress((void**)&p_proj, g_proj);
    cudaGetSymbolAddress((void**)&p_x2,   g_x2);
    cudaGetSymbolAddress((void**)&p_h,    g_h);
    cudaGetSymbolAddress((void**)&p_f1,   g_f1);
    cudaGetSymbolAddress((void**)&p_wt,   g_wt);

    cudaFuncSetAttribute(k_gemm_bf<0, __nv_bfloat16>, cudaFuncAttributeMaxDynamicSharedMemorySize, SMEM_GEMM);
    cudaFuncSetAttribute(k_gemm_bf<1, __nv_bfloat16>, cudaFuncAttributeMaxDynamicSharedMemorySize, SMEM_GEMM);
    cudaFuncSetAttribute(k_gemm_bf<2, float>,         cudaFuncAttributeMaxDynamicSharedMemorySize, SMEM_GEMM);
    cudaFuncSetAttribute(k_gemm_bf<3, float>,         cudaFuncAttributeMaxDynamicSharedMemorySize, SMEM_GEMM);

    // 0. transpose + bf16 weights (single launch)
    k_transpose_all<<<1728, dim3(32, 8)>>>(qkv_w, proj_w, fc1_w, fc2_w, p_wt);

    // 1. LN1 + shift + window partition
    k_ln1<<<Mrows, 128>>>(x, n1w, n1b, p_xw);

    // 2. QKV GEMM -> bf16
    k_gemm_bf<0, __nv_bfloat16><<<dim3(ThreeC/GBN, Mrows/GBM), 512, SMEM_GEMM>>>(
        p_xw, p_wt + WT_QKV, qkv_b, nullptr, p_qkv, Mrows, ThreeC, Cc);

    // 3. windowed attention -> bf16
    k_attn<<<(Bn * NWim) * NHd, 192>>>(p_qkv, rpb, p_attb);

    // 4. proj GEMM -> f32
    k_gemm_bf<2, float><<<dim3(Cc/GBN, Mrows/GBM), 512, SMEM_GEMM>>>(
        p_attb, p_wt + WT_PROJ, proj_b, nullptr, p_proj, Mrows, Cc, Cc);

    // 5+6. residual + reverse + unshift + LN2
    k_resid_ln2<<<Mrows, 128>>>(x, p_proj, n2w, n2b, p_x2, p_h);

    // 7. fc1 GEMM + GELU -> bf16
    k_gemm_bf<1, __nv_bfloat16><<<dim3(MLPH/GBN, Mrows/GBM), 512, SMEM_GEMM>>>(
        p_h, p_wt + WT_FC1, fc1_b, nullptr, p_f1, Mrows, MLPH, Cc);

    // 8. fc2 GEMM + bias + residual -> f32 out
    k_gemm_bf<3, float><<<dim3(Cc/GBN, Mrows/GBM), 512, SMEM_GEMM>>>(
        p_f1, p_wt + WT_FC2, fc2_b, p_x2, out, Mrows, Cc, MLPH);
}

// round 9
// speedup vs baseline: 7.6566x; 1.4172x over previous
#include <cuda_runtime.h>
#include <cuda_bf16.h>
#include <math.h>
#include <stdint.h>

// ---------------- problem constants ----------------
constexpr int Bn   = 32;
constexpr int Hh   = 56;
constexpr int Wd   = 56;
constexpr int Cc   = 384;
constexpr int NHd  = 12;
constexpr int WS   = 7;
constexpr int SS   = 3;
constexpr int Ntok = WS * WS;            // 49
constexpr int NWim = (Hh/WS) * (Wd/WS);  // 64
constexpr int HD   = Cc / NHd;           // 32
constexpr int MLPH = 4 * Cc;             // 1536
constexpr int Mrows = Bn * Hh * Wd;      // 100352
constexpr int ThreeC = 3 * Cc;           // 1152

// ---------------- scratch (device globals) ----------------
__device__ __nv_bfloat16 g_xw  [(size_t)Mrows * Cc];
__device__ __nv_bfloat16 g_qkv [(size_t)Mrows * ThreeC];
__device__ __nv_bfloat16 g_attb[(size_t)Mrows * Cc];
__device__ float         g_proj[(size_t)Mrows * Cc];
__device__ float         g_x2  [(size_t)Mrows * Cc];
__device__ __nv_bfloat16 g_h   [(size_t)Mrows * Cc];
__device__ __nv_bfloat16 g_f1  [(size_t)Mrows * MLPH];
constexpr size_t WT_QKV  = 0;
constexpr size_t WT_PROJ = WT_QKV  + (size_t)Cc * ThreeC;
constexpr size_t WT_FC1  = WT_PROJ + (size_t)Cc * Cc;
constexpr size_t WT_FC2  = WT_FC1  + (size_t)Cc * MLPH;
__device__ __nv_bfloat16 g_wt[WT_FC2 + (size_t)MLPH * Cc];

// ---------------- helpers ----------------
__device__ __forceinline__ uint32_t smem_u32(const void* p) {
    uint32_t a;
    asm("{ .reg .u64 t; cvta.to.shared.u64 t, %1; cvt.u32.u64 %0, t; }" : "=r"(a) : "l"(p));
    return a;
}
#define CP16(dst, src) asm volatile("cp.async.cg.shared.global [%0], [%1], 16;\n" :: "r"(dst), "l"(src))
#define CP_COMMIT()    asm volatile("cp.async.commit_group;\n" ::: "memory")
#define CP_WAIT2()     asm volatile("cp.async.wait_group 2;\n" ::: "memory")

__device__ __forceinline__ uint32_t swz64(uint32_t off) {
    return off ^ ((off >> 3) & 0x30);
}
__device__ __forceinline__ uint32_t swz128(uint32_t off) {
    return off ^ ((off >> 3) & 0x70);
}
__device__ __forceinline__ void ldsm_x4(uint32_t* r, uint32_t addr) {
    asm volatile("ldmatrix.sync.aligned.m8n8.x4.shared.b16 {%0,%1,%2,%3}, [%4];"
        : "=r"(r[0]), "=r"(r[1]), "=r"(r[2]), "=r"(r[3]) : "r"(addr));
}
__device__ __forceinline__ void ldsm_x4_t(uint32_t* r, uint32_t addr) {
    asm volatile("ldmatrix.sync.aligned.m8n8.x4.trans.shared.b16 {%0,%1,%2,%3}, [%4];"
        : "=r"(r[0]), "=r"(r[1]), "=r"(r[2]), "=r"(r[3]) : "r"(addr));
}
__device__ __forceinline__ void mma_bf16(float* d, const uint32_t* a,
                                         uint32_t b0, uint32_t b1) {
    asm volatile(
        "mma.sync.aligned.m16n8k16.row.col.f32.bf16.bf16.f32 "
        "{%0,%1,%2,%3}, {%4,%5,%6,%7}, {%8,%9}, {%0,%1,%2,%3};\n"
        : "+f"(d[0]), "+f"(d[1]), "+f"(d[2]), "+f"(d[3])
        : "r"(a[0]), "r"(a[1]), "r"(a[2]), "r"(a[3]), "r"(b0), "r"(b1));
}
__device__ __forceinline__ __nv_bfloat162 pack_bf2(float a, float b) {
    return __floats2bfloat162_rn(a, b);
}

// ---------------- single-launch weight transpose + bf16: W[K,N] -> Wt[N,K] ------
__global__ void k_transpose_all(const float* __restrict__ qkv_w, const float* __restrict__ proj_w,
                                const float* __restrict__ fc1_w, const float* __restrict__ fc2_w,
                                __nv_bfloat16* __restrict__ wt) {
    int t = blockIdx.x;
    const float* W; __nv_bfloat16* Wt; int K, N, tile, ntx;
    if (t < 432)       { W = qkv_w;  Wt = wt + WT_QKV;  K = Cc;   N = ThreeC; tile = t;        ntx = 36; }
    else if (t < 576)  { W = proj_w; Wt = wt + WT_PROJ; K = Cc;   N = Cc;     tile = t - 432;  ntx = 12; }
    else if (t < 1152) { W = fc1_w;  Wt = wt + WT_FC1;  K = Cc;   N = MLPH;   tile = t - 576;  ntx = 48; }
    else               { W = fc2_w;  Wt = wt + WT_FC2;  K = MLPH; N = Cc;     tile = t - 1152; ntx = 12; }
    int n0 = (tile % ntx) * 32, k0 = (tile / ntx) * 32;

    __shared__ float sm[32][33];
    int tx = threadIdx.x, ty = threadIdx.y;
    #pragma unroll
    for (int i = 0; i < 32; i += 8)
        sm[ty + i][tx] = W[(size_t)(k0 + ty + i) * N + n0 + tx];
    __syncthreads();
    #pragma unroll
    for (int i = 0; i < 32; i += 8)
        Wt[(size_t)(n0 + ty + i) * K + k0 + tx] = __float2bfloat16_rn(sm[tx][ty + i]);
}

// ---------------- bf16 mma.sync GEMM, 512 threads (16 warps) ----------------
constexpr int GBM = 256, GBN = 128;
constexpr int ASTB = GBM * 64;
constexpr int BSTB = GBN * 64;
constexpr int STB  = ASTB + BSTB;
constexpr int SMEM_GEMM = 4 * STB;

template <int OT, typename OutT>
__global__ __launch_bounds__(512, 1)
void k_gemm_bf(const __nv_bfloat16* __restrict__ A, const __nv_bfloat16* __restrict__ Wt,
               const float* __restrict__ bias, const float* __restrict__ res,
               OutT* __restrict__ Cm, int M, int N, int K) {
    extern __shared__ char smem[];
    uint32_t sbase = smem_u32(smem);

    const int tid  = threadIdx.x;
    const int lane = tid & 31, warp = tid >> 5;
    const int wm = warp >> 1, wn = warp & 1;
    const int g = lane >> 2, q = lane & 3;
    const int row0 = blockIdx.y * GBM, col0 = blockIdx.x * GBN;
    const int KT = K / 32;

    const __nv_bfloat16* Ab = A  + (size_t)row0 * K;
    const __nv_bfloat16* Bb = Wt + (size_t)col0 * K;

    uint32_t a_off[2], b_off[4];
    {
        int rowa = wm * 32 + (lane & 15);
        int sega = lane >> 4;
        #pragma unroll
        for (int mi = 0; mi < 2; mi++)
            a_off[mi] = swz64((uint32_t)(rowa + mi * 16) * 64 + sega * 16);
        int rowb = wn * 64 + (lane & 7) + ((lane >> 4) << 3);
        int segb = (lane >> 3) & 1;
        #pragma unroll
        for (int p = 0; p < 4; p++)
            b_off[p] = ASTB + swz64((uint32_t)(rowb + p * 16) * 64 + segb * 16);
    }

    float acc[2][8][4];
    #pragma unroll
    for (int i = 0; i < 2; i++)
        #pragma unroll
        for (int j = 0; j < 8; j++)
            #pragma unroll
            for (int r = 0; r < 4; r++) acc[i][j][r] = 0.f;

    auto load_stage = [&](int kt, int s) {
        uint32_t sA = sbase + (uint32_t)s * STB;
        uint32_t sB = sA + ASTB;
        const __nv_bfloat16* Ap = Ab + kt * 32;
        const __nv_bfloat16* Bp = Bb + kt * 32;
        #pragma unroll
        for (int i = 0; i < 2; i++) {
            int c = tid + i * 512, r = c >> 2, cc = c & 3;
            CP16(sA + swz64((uint32_t)(r * 64 + cc * 16)), Ap + (size_t)r * K + cc * 8);
        }
        {
            int r = tid >> 2, cc = tid & 3;
            CP16(sB + swz64((uint32_t)(r * 64 + cc * 16)), Bp + (size_t)r * K + cc * 8);
        }
    };

    load_stage(0, 0); CP_COMMIT();
    load_stage(1, 1); CP_COMMIT();
    load_stage(2, 2); CP_COMMIT();

    for (int kt = 0; kt < KT; kt++) {
        CP_WAIT2();
        __syncthreads();
        uint32_t st = sbase + (uint32_t)(kt & 3) * STB;
        #pragma unroll
        for (int ks = 0; ks < 2; ks++) {
            const uint32_t kx = (uint32_t)ks * 0x20;
            uint32_t a[2][4], b[4][4];
            #pragma unroll
            for (int mi = 0; mi < 2; mi++) ldsm_x4(a[mi], st + (a_off[mi] ^ kx));
            #pragma unroll
            for (int p = 0; p < 4; p++)    ldsm_x4(b[p],  st + (b_off[p]  ^ kx));
            #pragma unroll
            for (int mi = 0; mi < 2; mi++)
                #pragma unroll
                for (int p = 0; p < 4; p++) {
                    mma_bf16(acc[mi][2 * p],     a[mi], b[p][0], b[p][1]);
                    mma_bf16(acc[mi][2 * p + 1], a[mi], b[p][2], b[p][3]);
                }
        }
        if (kt + 3 < KT) load_stage(kt + 3, (kt + 3) & 3);
        CP_COMMIT();
    }

    #pragma unroll
    for (int mi = 0; mi < 2; mi++) {
        int r0 = row0 + wm * 32 + mi * 16 + g;
        #pragma unroll
        for (int ni = 0; ni < 8; ni++) {
            int c = col0 + wn * 64 + ni * 8 + q * 2;
            float b0 = bias[c], b1 = bias[c + 1];
            float v0 = acc[mi][ni][0] + b0;
            float v1 = acc[mi][ni][1] + b1;
            float v2 = acc[mi][ni][2] + b0;
            float v3 = acc[mi][ni][3] + b1;
            if (OT == 1) {
                v0 = 0.5f * v0 * (1.f + erff(v0 * 0.70710678118654752f));
                v1 = 0.5f * v1 * (1.f + erff(v1 * 0.70710678118654752f));
                v2 = 0.5f * v2 * (1.f + erff(v2 * 0.70710678118654752f));
                v3 = 0.5f * v3 * (1.f + erff(v3 * 0.70710678118654752f));
            }
            if (OT == 3) {
                float2 ra = *(const float2*)&res[(size_t)r0 * N + c];
                float2 rb = *(const float2*)&res[(size_t)(r0 + 8) * N + c];
                v0 += ra.x; v1 += ra.y; v2 += rb.x; v3 += rb.y;
            }
            if (OT <= 1) {
                *(__nv_bfloat162*)&((__nv_bfloat16*)Cm)[(size_t)r0 * N + c]       = pack_bf2(v0, v1);
                *(__nv_bfloat162*)&((__nv_bfloat16*)Cm)[(size_t)(r0 + 8) * N + c] = pack_bf2(v2, v3);
            } else {
                *(float2*)&((float*)Cm)[(size_t)r0 * N + c]       = make_float2(v0, v1);
                *(float2*)&((float*)Cm)[(size_t)(r0 + 8) * N + c] = make_float2(v2, v3);
            }
        }
    }
}

// ---------------- block reduce (sum, sumsq) over 128 threads ----------------
__device__ __forceinline__ void blockReduce2(float& s, float& s2) {
    #pragma unroll
    for (int o = 16; o > 0; o >>= 1) {
        s  += __shfl_down_sync(0xFFFFFFFFu, s,  o);
        s2 += __shfl_down_sync(0xFFFFFFFFu, s2, o);
    }
    __shared__ float sh[4][2];
    int w = threadIdx.x >> 5, l = threadIdx.x & 31;
    if (l == 0) { sh[w][0] = s; sh[w][1] = s2; }
    __syncthreads();
    if (threadIdx.x == 0) {
        float a = 0.f, b = 0.f;
        #pragma unroll
        for (int i = 0; i < 4; i++) { a += sh[i][0]; b += sh[i][1]; }
        sh[0][0] = a; sh[0][1] = b;
    }
    __syncthreads();
    s = sh[0][0]; s2 = sh[0][1];
}

// ---------------- LN1 + shift + window partition -> bf16 ----------------
__global__ void k_ln1(const float* __restrict__ x, const float* __restrict__ w,
                      const float* __restrict__ bi, __nv_bfloat16* __restrict__ out) {
    int t = blockIdx.x;
    int widx = t / Ntok, n = t % Ntok;
    int b  = widx / NWim, wi = widx % NWim;
    int wh = wi / 8, ww = wi % 8;
    int r  = wh * WS + n / WS, c = ww * WS + n % WS;
    int sh = (r + SS) % Hh, sw = (c + SS) % Wd;
    const float* src = x + ((size_t)b * (Hh*Wd) + sh * Wd + sw) * Cc;

    int tid = threadIdx.x;
    float vals[3]; float s = 0.f, s2 = 0.f;
    #pragma unroll
    for (int i = 0; i < 3; i++) {
        float v = src[tid + i * 128];
        vals[i] = v; s += v; s2 += v * v;
    }
    blockReduce2(s, s2);
    float mean = s * (1.f / Cc);
    float var  = s2 * (1.f / Cc) - mean * mean;
    float inv  = rsqrtf(var + 1e-5f);
    __nv_bfloat16* dst = out + (size_t)t * Cc;
    #pragma unroll
    for (int i = 0; i < 3; i++) {
        int cI = tid + i * 128;
        dst[cI] = __float2bfloat16_rn((vals[i] - mean) * inv * w[cI] + bi[cI]);
    }
}

// ---------------- fused residual(+reverse+unshift) + LN2 ----------------
__global__ void k_resid_ln2(const float* __restrict__ x, const float* __restrict__ proj,
                            const float* __restrict__ w, const float* __restrict__ bi,
                            float* __restrict__ x2, __nv_bfloat16* __restrict__ hout) {
    int t = blockIdx.x;
    int b = t / (Hh * Wd), p = t % (Hh * Wd);
    int h = p / Wd, ww0 = p % Wd;
    int sh = (h + Hh - SS) % Hh, sw = (ww0 + Wd - SS) % Wd;
    int wh = sh / WS, ww = sw / WS;
    int tok = ((b * 8 + wh) * 8 + ww) * Ntok + (sh % WS) * WS + (sw % WS);
    const float* src1 = x    + (size_t)t   * Cc;
    const float* src2 = proj + (size_t)tok * Cc;

    int tid = threadIdx.x;
    float vals[3]; float s = 0.f, s2 = 0.f;
    #pragma unroll
    for (int i = 0; i < 3; i++) {
        int cI = tid + i * 128;
        float v = src1[cI] + src2[cI];
        vals[i] = v; s += v; s2 += v * v;
    }
    blockReduce2(s, s2);
    float mean = s * (1.f / Cc);
    float var  = s2 * (1.f / Cc) - mean * mean;
    float inv  = rsqrtf(var + 1e-5f);
    float* d1 = x2 + (size_t)t * Cc;
    __nv_bfloat16* d2 = hout + (size_t)t * Cc;
    #pragma unroll
    for (int i = 0; i < 3; i++) {
        int cI = tid + i * 128;
        d1[cI] = vals[i];
        d2[cI] = __float2bfloat16_rn((vals[i] - mean) * inv * w[cI] + bi[cI]);
    }
}

// ---------------- tensor-core attention: block = (window, head), 128 thr -------
// smem: Q 0 (4KB, 64B rows swz64) | K 4096 | V 8192 | P 12288 (8KB, 128B rows swz128)
//       | bias 20480 (169 f32) | reg 21160 (49 int)
__global__ __launch_bounds__(128)
void k_attn(const __nv_bfloat16* __restrict__ qkv, const float* __restrict__ rpb,
            __nv_bfloat16* __restrict__ out) {
    __shared__ __align__(1024) char smem[21504];
    uint32_t sb = smem_u32(smem);
    float* sbias = (float*)(smem + 20480);
    int*   sreg  = (int*)(smem + 21160);

    int blk = blockIdx.x;
    int widx = blk / NHd, hh = blk % NHd;
    int wi = widx % NWim;
    int wh = wi / 8, ww = wi % 8;
    int tid = threadIdx.x, lane = tid & 31, warp = tid >> 5;
    int g = lane >> 2, q = lane & 3;

    // ---- load Q,K,V into swizzled smem (rows 0-48), zero pad rows 49-63 ----
    const __nv_bfloat16* base0 = qkv + (size_t)(widx * Ntok) * ThreeC + hh * HD;
    for (int idx = tid; idx < 196; idx += 128) {
        int row = idx >> 2, seg = idx & 3;
        const __nv_bfloat16* p = base0 + (size_t)row * ThreeC + seg * 8;
        uint32_t d = swz64((uint32_t)(row * 64 + seg * 16));
        *(uint4*)(smem + d)        = *(const uint4*)(p);
        *(uint4*)(smem + 4096 + d) = *(const uint4*)(p + Cc);
        *(uint4*)(smem + 8192 + d) = *(const uint4*)(p + 2 * Cc);
    }
    for (int idx = 196 + tid; idx < 256; idx += 128) {
        int row = idx >> 2, seg = idx & 3;
        uint32_t d = swz64((uint32_t)(row * 64 + seg * 16));
        uint4 z = make_uint4(0, 0, 0, 0);
        *(uint4*)(smem + d)        = z;
        *(uint4*)(smem + 4096 + d) = z;
        *(uint4*)(smem + 8192 + d) = z;
    }
    if (tid < Ntok) {
        int r = wh * WS + tid / WS, c = ww * WS + tid % WS;
        int hr = (r < Hh - WS) ? 0 : ((r < Hh - SS) ? 1 : 2);
        int wr = (c < Wd - WS) ? 0 : ((c < Wd - SS) ? 1 : 2);
        sreg[tid] = hr * 3 + wr;
    }
    for (int idx = tid; idx < 169; idx += 128)
        sbias[idx] = rpb[idx * NHd + hh];
    __syncthreads();

    // ---- S = Q K^T (64x64, K=32) : warp -> 16-row m-tile ----
    float acc[8][4];
    #pragma unroll
    for (int i = 0; i < 8; i++)
        #pragma unroll
        for (int r = 0; r < 4; r++) acc[i][r] = 0.f;
    {
        uint32_t aoff = swz64((uint32_t)(warp * 16 + (lane & 15)) * 64 + (lane >> 4) * 16);
        int rowb = (lane & 7) + ((lane >> 4) << 3);
        uint32_t segb = ((lane >> 3) & 1) * 16;
        uint32_t boff[4];
        #pragma unroll
        for (int p = 0; p < 4; p++)
            boff[p] = 4096u + swz64((uint32_t)(rowb + p * 16) * 64 + segb);
        #pragma unroll
        for (int kk = 0; kk < 2; kk++) {
            uint32_t kx = (uint32_t)kk * 32;
            uint32_t a[4];
            ldsm_x4(a, sb + (aoff ^ kx));
            #pragma unroll
            for (int p = 0; p < 4; p++) {
                uint32_t b[4];
                ldsm_x4(b, sb + (boff[p] ^ kx));
                mma_bf16(acc[2 * p],     a, b[0], b[1]);
                mma_bf16(acc[2 * p + 1], a, b[2], b[3]);
            }
        }
    }

    // ---- scale + bias + mask + softmax (rows i1, i2 distributed over quad) ----
    const float scl = 0.17677669529663687f;
    int i1 = warp * 16 + g, i2 = i1 + 8;
    bool v1 = i1 < Ntok, v2 = i2 < Ntok;
    int i1d = i1 / 7, i1m = i1 - i1d * 7, r1 = v1 ? sreg[i1] : 0;
    int i2d = i2 / 7, i2m = i2 - i2d * 7, r2 = v2 ? sreg[i2] : 0;
    float mx1 = -1e30f, mx2 = -1e30f;
    #pragma unroll
    for (int ni = 0; ni < 8; ni++) {
        #pragma unroll
        for (int e = 0; e < 2; e++) {
            int j = ni * 8 + q * 2 + e;
            if (j < Ntok) {
                int jd = j / 7, jm = j - jd * 7;
                int rj = sreg[j];
                float b1v = sbias[(i1d - jd + 6) * 13 + (i1m - jm + 6)];
                float t1 = acc[ni][e] * scl + b1v + ((r1 != rj) ? -100.f : 0.f);
                acc[ni][e] = t1; mx1 = fmaxf(mx1, t1);
                float b2v = sbias[(i2d - jd + 6) * 13 + (i2m - jm + 6)];
                float t2 = acc[ni][e + 2] * scl + b2v + ((r2 != rj) ? -100.f : 0.f);
                acc[ni][e + 2] = t2; mx2 = fmaxf(mx2, t2);
            } else {
                acc[ni][e] = -1e30f; acc[ni][e + 2] = -1e30f;
            }
        }
    }
    mx1 = fmaxf(mx1, __shfl_xor_sync(0xFFFFFFFFu, mx1, 1));
    mx1 = fmaxf(mx1, __shfl_xor_sync(0xFFFFFFFFu, mx1, 2));
    mx2 = fmaxf(mx2, __shfl_xor_sync(0xFFFFFFFFu, mx2, 1));
    mx2 = fmaxf(mx2, __shfl_xor_sync(0xFFFFFFFFu, mx2, 2));
    float s1 = 0.f, s2 = 0.f;
    #pragma unroll
    for (int ni = 0; ni < 8; ni++) {
        #pragma unroll
        for (int e = 0; e < 2; e++) {
            float e1 = __expf(acc[ni][e] - mx1);     acc[ni][e] = e1;     s1 += e1;
            float e2 = __expf(acc[ni][e + 2] - mx2); acc[ni][e + 2] = e2; s2 += e2;
        }
    }
    s1 += __shfl_xor_sync(0xFFFFFFFFu, s1, 1);
    s1 += __shfl_xor_sync(0xFFFFFFFFu, s1, 2);
    s2 += __shfl_xor_sync(0xFFFFFFFFu, s2, 1);
    s2 += __shfl_xor_sync(0xFFFFFFFFu, s2, 2);
    float n1 = v1 ? (1.f / s1) : 0.f;
    float n2 = v2 ? (1.f / s2) : 0.f;

    // ---- store P (bf16) into swizzled 128B-row buffer (warp-private rows) ----
    #pragma unroll
    for (int ni = 0; ni < 8; ni++) {
        uint32_t cb = (uint32_t)(ni * 8 + q * 2) * 2;
        uint32_t o1 = 12288u + swz128((uint32_t)i1 * 128 + cb);
        uint32_t o2 = 12288u + swz128((uint32_t)i2 * 128 + cb);
        *(__nv_bfloat162*)(smem + o1) = pack_bf2(acc[ni][0] * n1, acc[ni][1] * n1);
        *(__nv_bfloat162*)(smem + o2) = pack_bf2(acc[ni][2] * n2, acc[ni][3] * n2);
    }
    __syncwarp();

    // ---- O = P V  (64x32, K=64) ----
    float acc2[4][4];
    #pragma unroll
    for (int i = 0; i < 4; i++)
        #pragma unroll
        for (int r = 0; r < 4; r++) acc2[i][r] = 0.f;
    {
        uint32_t a2off = 12288u + swz128((uint32_t)(warp * 16 + (lane & 15)) * 128 + (lane >> 4) * 16);
        int rv = (lane & 7) + ((lane >> 3) & 1) * 8;
        uint32_t dv8 = (uint32_t)((lane >> 4) << 3);
        uint32_t voff0 = 8192u + swz64((uint32_t)rv * 64 + dv8 * 2);
        uint32_t voff1 = 8192u + swz64((uint32_t)rv * 64 + (16 + dv8) * 2);
        #pragma unroll
        for (int ks = 0; ks < 4; ks++) {
            uint32_t a2[4], b0[4], b1[4];
            ldsm_x4(a2, sb + (a2off ^ ((uint32_t)ks * 32)));
            ldsm_x4_t(b0, sb + voff0 + (uint32_t)ks * 1024);
            ldsm_x4_t(b1, sb + voff1 + (uint32_t)ks * 1024);
            mma_bf16(acc2[0], a2, b0[0], b0[1]);
            mma_bf16(acc2[1], a2, b0[2], b0[3]);
            mma_bf16(acc2[2], a2, b1[0], b1[1]);
            mma_bf16(acc2[3], a2, b1[2], b1[3]);
        }
    }

    // ---- store O rows < 49 ----
    if (v1) {
        __nv_bfloat16* d = out + (size_t)(widx * Ntok + i1) * Cc + hh * HD + q * 2;
        #pragma unroll
        for (int dt = 0; dt < 4; dt++)
            *(__nv_bfloat162*)(d + dt * 8) = pack_bf2(acc2[dt][0], acc2[dt][1]);
    }
    if (v2) {
        __nv_bfloat16* d = out + (size_t)(widx * Ntok + i2) * Cc + hh * HD + q * 2;
        #pragma unroll
        for (int dt = 0; dt < 4; dt++)
            *(__nv_bfloat162*)(d + dt * 8) = pack_bf2(acc2[dt][2], acc2[dt][3]);
    }
}

// ---------------- host launch ----------------
extern "C" void kernel_launch(void* const* d_in, const int* in_sizes, int n_in,
                              void* d_out, int out_size) {
    const float* x      = (const float*)d_in[0];
    const float* n1w    = (const float*)d_in[1];
    const float* n1b    = (const float*)d_in[2];
    const float* qkv_w  = (const float*)d_in[3];
    const float* qkv_b  = (const float*)d_in[4];
    const float* rpb    = (const float*)d_in[5];
    const float* proj_w = (const float*)d_in[6];
    const float* proj_b = (const float*)d_in[7];
    const float* n2w    = (const float*)d_in[8];
    const float* n2b    = (const float*)d_in[9];
    const float* fc1_w  = (const float*)d_in[10];
    const float* fc1_b  = (const float*)d_in[11];
    const float* fc2_w  = (const float*)d_in[12];
    const float* fc2_b  = (const float*)d_in[13];
    float* out = (float*)d_out;

    __nv_bfloat16 *p_xw, *p_qkv, *p_attb, *p_h, *p_f1, *p_wt;
    float *p_proj, *p_x2;
    cudaGetSymbolAddress((void**)&p_xw,   g_xw);
    cudaGetSymbolAddress((void**)&p_qkv,  g_qkv);
    cudaGetSymbolAddress((void**)&p_attb, g_attb);
    cudaGetSymbolAddress((void**)&p_proj, g_proj);
    cudaGetSymbolAddress((void**)&p_x2,   g_x2);
    cudaGetSymbolAddress((void**)&p_h,    g_h);
    cudaGetSymbolAddress((void**)&p_f1,   g_f1);
    cudaGetSymbolAddress((void**)&p_wt,   g_wt);

    cudaFuncSetAttribute(k_gemm_bf<0, __nv_bfloat16>, cudaFuncAttributeMaxDynamicSharedMemorySize, SMEM_GEMM);
    cudaFuncSetAttribute(k_gemm_bf<1, __nv_bfloat16>, cudaFuncAttributeMaxDynamicSharedMemorySize, SMEM_GEMM);
    cudaFuncSetAttribute(k_gemm_bf<2, float>,         cudaFuncAttributeMaxDynamicSharedMemorySize, SMEM_GEMM);
    cudaFuncSetAttribute(k_gemm_bf<3, float>,         cudaFuncAttributeMaxDynamicSharedMemorySize, SMEM_GEMM);

    // 0. transpose + bf16 weights (single launch)
    k_transpose_all<<<1728, dim3(32, 8)>>>(qkv_w, proj_w, fc1_w, fc2_w, p_wt);

    // 1. LN1 + shift + window partition
    k_ln1<<<Mrows, 128>>>(x, n1w, n1b, p_xw);

    // 2. QKV GEMM -> bf16
    k_gemm_bf<0, __nv_bfloat16><<<dim3(ThreeC/GBN, Mrows/GBM), 512, SMEM_GEMM>>>(
        p_xw, p_wt + WT_QKV, qkv_b, nullptr, p_qkv, Mrows, ThreeC, Cc);

    // 3. tensor-core windowed attention -> bf16
    k_attn<<<(Bn * NWim) * NHd, 128>>>(p_qkv, rpb, p_attb);

    // 4. proj GEMM -> f32
    k_gemm_bf<2, float><<<dim3(Cc/GBN, Mrows/GBM), 512, SMEM_GEMM>>>(
        p_attb, p_wt + WT_PROJ, proj_b, nullptr, p_proj, Mrows, Cc, Cc);

    // 5+6. residual + reverse + unshift + LN2
    k_resid_ln2<<<Mrows, 128>>>(x, p_proj, n2w, n2b, p_x2, p_h);

    // 7. fc1 GEMM + GELU -> bf16
    k_gemm_bf<1, __nv_bfloat16><<<dim3(MLPH/GBN, Mrows/GBM), 512, SMEM_GEMM>>>(
        p_h, p_wt + WT_FC1, fc1_b, nullptr, p_f1, Mrows, MLPH, Cc);

    // 8. fc2 GEMM + bias + residual -> f32 out
    k_gemm_bf<3, float><<<dim3(Cc/GBN, Mrows/GBM), 512, SMEM_GEMM>>>(
        p_f1, p_wt + WT_FC2, fc2_b, p_x2, out, Mrows, Cc, MLPH);
}

// round 12
// speedup vs baseline: 8.1647x; 1.0663x over previous
#include <cuda_runtime.h>
#include <cuda_bf16.h>
#include <math.h>
#include <stdint.h>

// ---------------- problem constants ----------------
constexpr int Bn   = 32;
constexpr int Hh   = 56;
constexpr int Wd   = 56;
constexpr int Cc   = 384;
constexpr int NHd  = 12;
constexpr int WS   = 7;
constexpr int SS   = 3;
constexpr int Ntok = WS * WS;            // 49
constexpr int NWim = (Hh/WS) * (Wd/WS);  // 64
constexpr int HD   = Cc / NHd;           // 32
constexpr int MLPH = 4 * Cc;             // 1536
constexpr int Mrows = Bn * Hh * Wd;      // 100352
constexpr int ThreeC = 3 * Cc;           // 1152

// ---------------- scratch (device globals) ----------------
__device__ __nv_bfloat16 g_xw  [(size_t)Mrows * Cc];      // ln1 out (window order)
__device__ __nv_bfloat16 g_qkv [(size_t)Mrows * ThreeC];
__device__ __nv_bfloat16 g_attb[(size_t)Mrows * Cc];
__device__ float         g_x2w [(size_t)Mrows * Cc];      // residual carrier (window order)
__device__ __nv_bfloat16 g_h   [(size_t)Mrows * Cc];      // ln2 out (window order)
__device__ __nv_bfloat16 g_f1  [(size_t)Mrows * MLPH];
constexpr size_t WT_QKV  = 0;
constexpr size_t WT_PROJ = WT_QKV  + (size_t)Cc * ThreeC;
constexpr size_t WT_FC1  = WT_PROJ + (size_t)Cc * Cc;
constexpr size_t WT_FC2  = WT_FC1  + (size_t)Cc * MLPH;
__device__ __nv_bfloat16 g_wt[WT_FC2 + (size_t)MLPH * Cc];

// ---------------- helpers ----------------
__device__ __forceinline__ uint32_t smem_u32(const void* p) {
    uint32_t a;
    asm("{ .reg .u64 t; cvta.to.shared.u64 t, %1; cvt.u32.u64 %0, t; }" : "=r"(a) : "l"(p));
    return a;
}
#define CP16(dst, src) asm volatile("cp.async.cg.shared.global [%0], [%1], 16;\n" :: "r"(dst), "l"(src))
#define CP_COMMIT()    asm volatile("cp.async.commit_group;\n" ::: "memory")
#define CP_WAIT1()     asm volatile("cp.async.wait_group 1;\n" ::: "memory")

__device__ __forceinline__ uint32_t swz64(uint32_t off) {
    return off ^ ((off >> 3) & 0x30);
}
__device__ __forceinline__ uint32_t swz128(uint32_t off) {
    return off ^ ((off >> 3) & 0x70);
}
__device__ __forceinline__ void ldsm_x4(uint32_t* r, uint32_t addr) {
    asm volatile("ldmatrix.sync.aligned.m8n8.x4.shared.b16 {%0,%1,%2,%3}, [%4];"
        : "=r"(r[0]), "=r"(r[1]), "=r"(r[2]), "=r"(r[3]) : "r"(addr));
}
__device__ __forceinline__ void ldsm_x4_t(uint32_t* r, uint32_t addr) {
    asm volatile("ldmatrix.sync.aligned.m8n8.x4.trans.shared.b16 {%0,%1,%2,%3}, [%4];"
        : "=r"(r[0]), "=r"(r[1]), "=r"(r[2]), "=r"(r[3]) : "r"(addr));
}
__device__ __forceinline__ void mma_bf16(float* d, const uint32_t* a,
                                         uint32_t b0, uint32_t b1) {
    asm volatile(
        "mma.sync.aligned.m16n8k16.row.col.f32.bf16.bf16.f32 "
        "{%0,%1,%2,%3}, {%4,%5,%6,%7}, {%8,%9}, {%0,%1,%2,%3};\n"
        : "+f"(d[0]), "+f"(d[1]), "+f"(d[2]), "+f"(d[3])
        : "r"(a[0]), "r"(a[1]), "r"(a[2]), "r"(a[3]), "r"(b0), "r"(b1));
}
__device__ __forceinline__ __nv_bfloat162 pack_bf2(float a, float b) {
    return __floats2bfloat162_rn(a, b);
}
// window-order token -> image-order token (roll(+SS) of window reverse)
__device__ __forceinline__ int w2i(int t) {
    int widx = t / Ntok, n = t - widx * Ntok;
    int b = widx >> 6, wi = widx & 63;
    int r = (wi >> 3) * WS + n / WS;
    int c = (wi & 7) * WS + n % WS;
    int sh = r + SS; if (sh >= Hh) sh -= Hh;
    int sw = c + SS; if (sw >= Wd) sw -= Wd;
    return b * (Hh * Wd) + sh * Wd + sw;
}

// ---------------- single-launch weight transpose + bf16: W[K,N] -> Wt[N,K] ------
__global__ void k_transpose_all(const float* __restrict__ qkv_w, const float* __restrict__ proj_w,
                                const float* __restrict__ fc1_w, const float* __restrict__ fc2_w,
                                __nv_bfloat16* __restrict__ wt) {
    int t = blockIdx.x;
    const float* W; __nv_bfloat16* Wt; int K, N, tile, ntx;
    if (t < 432)       { W = qkv_w;  Wt = wt + WT_QKV;  K = Cc;   N = ThreeC; tile = t;        ntx = 36; }
    else if (t < 576)  { W = proj_w; Wt = wt + WT_PROJ; K = Cc;   N = Cc;     tile = t - 432;  ntx = 12; }
    else if (t < 1152) { W = fc1_w;  Wt = wt + WT_FC1;  K = Cc;   N = MLPH;   tile = t - 576;  ntx = 48; }
    else               { W = fc2_w;  Wt = wt + WT_FC2;  K = MLPH; N = Cc;     tile = t - 1152; ntx = 12; }
    int n0 = (tile % ntx) * 32, k0 = (tile / ntx) * 32;

    __shared__ float sm[32][33];
    int tx = threadIdx.x, ty = threadIdx.y;
    #pragma unroll
    for (int i = 0; i < 32; i += 8)
        sm[ty + i][tx] = W[(size_t)(k0 + ty + i) * N + n0 + tx];
    __syncthreads();
    #pragma unroll
    for (int i = 0; i < 32; i += 8)
        Wt[(size_t)(n0 + ty + i) * K + k0 + tx] = __float2bfloat16_rn(sm[tx][ty + i]);
}

// ---------------- bf16 mma.sync GEMM, 128x128 tile, 256 thr, 2 CTAs/SM ----------
// 8 warps (4M x 2N), warp tile 32x64, BK=32, 3-stage cp.async, 48KB smem.
// OT: 0 = bias,bf16 ; 1 = bias+gelu,bf16 ;
//     4 = bias + gather-res(x, image order) -> f32 window order (proj)
//     5 = bias + res(x2w) -> f32 scattered to image order (fc2 -> d_out)
constexpr int GBM = 128, GBN = 128;
constexpr int ASTB = GBM * 64;            // 8192
constexpr int BSTB = GBN * 64;            // 8192
constexpr int STB  = ASTB + BSTB;         // 16384
constexpr int SMEM_GEMM = 3 * STB;        // 49152

template <int OT, typename OutT>
__global__ __launch_bounds__(256, 2)
void k_gemm_bf(const __nv_bfloat16* __restrict__ A, const __nv_bfloat16* __restrict__ Wt,
               const float* __restrict__ bias, const float* __restrict__ res,
               OutT* __restrict__ Cm, int M, int N, int K) {
    extern __shared__ char smem[];
    uint32_t sbase = smem_u32(smem);

    const int tid  = threadIdx.x;
    const int lane = tid & 31, warp = tid >> 5;
    const int wm = warp >> 1, wn = warp & 1;      // 4 M-warps x 2 N-warps
    const int g = lane >> 2, q = lane & 3;
    const int row0 = blockIdx.y * GBM, col0 = blockIdx.x * GBN;
    const int KT = K / 32;

    const __nv_bfloat16* Ab = A  + (size_t)row0 * K;
    const __nv_bfloat16* Bb = Wt + (size_t)col0 * K;

    uint32_t a_off[2], b_off[4];
    {
        int rowa = wm * 32 + (lane & 15);
        int sega = lane >> 4;
        #pragma unroll
        for (int mi = 0; mi < 2; mi++)
            a_off[mi] = swz64((uint32_t)(rowa + mi * 16) * 64 + sega * 16);
        int rowb = wn * 64 + (lane & 7) + ((lane >> 4) << 3);
        int segb = (lane >> 3) & 1;
        #pragma unroll
        for (int p = 0; p < 4; p++)
            b_off[p] = ASTB + swz64((uint32_t)(rowb + p * 16) * 64 + segb * 16);
    }

    float acc[2][8][4];
    #pragma unroll
    for (int i = 0; i < 2; i++)
        #pragma unroll
        for (int j = 0; j < 8; j++)
            #pragma unroll
            for (int r = 0; r < 4; r++) acc[i][j][r] = 0.f;

    auto load_stage = [&](int kt, int s) {
        uint32_t sA = sbase + (uint32_t)s * STB;
        uint32_t sB = sA + ASTB;
        const __nv_bfloat16* Ap = Ab + kt * 32;
        const __nv_bfloat16* Bp = Bb + kt * 32;
        #pragma unroll
        for (int i = 0; i < 2; i++) {          // A: 512 chunks
            int c = tid + i * 256, r = c >> 2, cc = c & 3;
            CP16(sA + swz64((uint32_t)(r * 64 + cc * 16)), Ap + (size_t)r * K + cc * 8);
        }
        #pragma unroll
        for (int i = 0; i < 2; i++) {          // B: 512 chunks
            int c = tid + i * 256, r = c >> 2, cc = c & 3;
            CP16(sB + swz64((uint32_t)(r * 64 + cc * 16)), Bp + (size_t)r * K + cc * 8);
        }
    };

    load_stage(0, 0); CP_COMMIT();
    load_stage(1, 1); CP_COMMIT();

    int st_idx = 0;
    for (int kt = 0; kt < KT; kt++) {
        CP_WAIT1();
        __syncthreads();
        uint32_t st = sbase + (uint32_t)st_idx * STB;
        #pragma unroll
        for (int ks = 0; ks < 2; ks++) {
            const uint32_t kx = (uint32_t)ks * 0x20;
            uint32_t a[2][4], b[4][4];
            #pragma unroll
            for (int mi = 0; mi < 2; mi++) ldsm_x4(a[mi], st + (a_off[mi] ^ kx));
            #pragma unroll
            for (int p = 0; p < 4; p++)    ldsm_x4(b[p],  st + (b_off[p]  ^ kx));
            #pragma unroll
            for (int mi = 0; mi < 2; mi++)
                #pragma unroll
                for (int p = 0; p < 4; p++) {
                    mma_bf16(acc[mi][2 * p],     a[mi], b[p][0], b[p][1]);
                    mma_bf16(acc[mi][2 * p + 1], a[mi], b[p][2], b[p][3]);
                }
        }
        if (kt + 2 < KT) {
            int s2 = st_idx + 2; if (s2 >= 3) s2 -= 3;
            load_stage(kt + 2, s2);
        }
        CP_COMMIT();
        if (++st_idx == 3) st_idx = 0;
    }

    // ---- epilogue ----
    #pragma unroll
    for (int mi = 0; mi < 2; mi++) {
        int rA = row0 + wm * 32 + mi * 16 + g;
        int rB = rA + 8;
        const float* resA = nullptr; const float* resB = nullptr;
        OutT* outA; OutT* outB;
        if (OT == 4) {
            resA = res + (size_t)w2i(rA) * N;
            resB = res + (size_t)w2i(rB) * N;
            outA = Cm + (size_t)rA * N; outB = Cm + (size_t)rB * N;
        } else if (OT == 5) {
            resA = res + (size_t)rA * N;
            resB = res + (size_t)rB * N;
            outA = Cm + (size_t)w2i(rA) * N; outB = Cm + (size_t)w2i(rB) * N;
        } else {
            outA = Cm + (size_t)rA * N; outB = Cm + (size_t)rB * N;
        }
        #pragma unroll
        for (int ni = 0; ni < 8; ni++) {
            int c = col0 + wn * 64 + ni * 8 + q * 2;
            float b0 = bias[c], b1 = bias[c + 1];
            float v0 = acc[mi][ni][0] + b0;
            float v1 = acc[mi][ni][1] + b1;
            float v2 = acc[mi][ni][2] + b0;
            float v3 = acc[mi][ni][3] + b1;
            if (OT == 1) {
                v0 = 0.5f * v0 * (1.f + erff(v0 * 0.70710678118654752f));
                v1 = 0.5f * v1 * (1.f + erff(v1 * 0.70710678118654752f));
                v2 = 0.5f * v2 * (1.f + erff(v2 * 0.70710678118654752f));
                v3 = 0.5f * v3 * (1.f + erff(v3 * 0.70710678118654752f));
            }
            if (OT >= 4) {
                float2 ra = *(const float2*)&resA[c];
                float2 rb = *(const float2*)&resB[c];
                v0 += ra.x; v1 += ra.y; v2 += rb.x; v3 += rb.y;
            }
            if (OT <= 1) {
                *(__nv_bfloat162*)&((__nv_bfloat16*)outA)[c] = pack_bf2(v0, v1);
                *(__nv_bfloat162*)&((__nv_bfloat16*)outB)[c] = pack_bf2(v2, v3);
            } else {
                *(float2*)&((float*)outA)[c] = make_float2(v0, v1);
                *(float2*)&((float*)outB)[c] = make_float2(v2, v3);
            }
        }
    }
}

// ---------------- block reduce (sum, sumsq) over 128 threads ----------------
__device__ __forceinline__ void blockReduce2(float& s, float& s2) {
    #pragma unroll
    for (int o = 16; o > 0; o >>= 1) {
        s  += __shfl_down_sync(0xFFFFFFFFu, s,  o);
        s2 += __shfl_down_sync(0xFFFFFFFFu, s2, o);
    }
    __shared__ float sh[4][2];
    int w = threadIdx.x >> 5, l = threadIdx.x & 31;
    if (l == 0) { sh[w][0] = s; sh[w][1] = s2; }
    __syncthreads();
    if (threadIdx.x == 0) {
        float a = 0.f, b = 0.f;
        #pragma unroll
        for (int i = 0; i < 4; i++) { a += sh[i][0]; b += sh[i][1]; }
        sh[0][0] = a; sh[0][1] = b;
    }
    __syncthreads();
    s = sh[0][0]; s2 = sh[0][1];
}

// ---------------- LN1 + shift + window partition -> bf16 ----------------
__global__ void k_ln1(const float* __restrict__ x, const float* __restrict__ w,
                      const float* __restrict__ bi, __nv_bfloat16* __restrict__ out) {
    int t = blockIdx.x;
    const float* src = x + (size_t)w2i(t) * Cc;

    int tid = threadIdx.x;
    float vals[3]; float s = 0.f, s2 = 0.f;
    #pragma unroll
    for (int i = 0; i < 3; i++) {
        float v = src[tid + i * 128];
        vals[i] = v; s += v; s2 += v * v;
    }
    blockReduce2(s, s2);
    float mean = s * (1.f / Cc);
    float var  = s2 * (1.f / Cc) - mean * mean;
    float inv  = rsqrtf(var + 1e-5f);
    __nv_bfloat16* dst = out + (size_t)t * Cc;
    #pragma unroll
    for (int i = 0; i < 3; i++) {
        int cI = tid + i * 128;
        dst[cI] = __float2bfloat16_rn((vals[i] - mean) * inv * w[cI] + bi[cI]);
    }
}

// ---------------- LN2 (window order rows, x2w -> h bf16) ----------------
__global__ void k_ln2(const float* __restrict__ x2w, const float* __restrict__ w,
                      const float* __restrict__ bi, __nv_bfloat16* __restrict__ hout) {
    int t = blockIdx.x;
    const float* src = x2w + (size_t)t * Cc;
    int tid = threadIdx.x;
    float vals[3]; float s = 0.f, s2 = 0.f;
    #pragma unroll
    for (int i = 0; i < 3; i++) {
        float v = src[tid + i * 128];
        vals[i] = v; s += v; s2 += v * v;
    }
    blockReduce2(s, s2);
    float mean = s * (1.f / Cc);
    float var  = s2 * (1.f / Cc) - mean * mean;
    float inv  = rsqrtf(var + 1e-5f);
    __nv_bfloat16* dst = hout + (size_t)t * Cc;
    #pragma unroll
    for (int i = 0; i < 3; i++) {
        int cI = tid + i * 128;
        dst[cI] = __float2bfloat16_rn((vals[i] - mean) * inv * w[cI] + bi[cI]);
    }
}

// ---------------- tensor-core attention: block = (window, head), 128 thr -------
__global__ __launch_bounds__(128)
void k_attn(const __nv_bfloat16* __restrict__ qkv, const float* __restrict__ rpb,
            __nv_bfloat16* __restrict__ out) {
    __shared__ __align__(1024) char smem[21504];
    uint32_t sb = smem_u32(smem);
    float* sbias = (float*)(smem + 20480);
    int*   sreg  = (int*)(smem + 21160);

    int blk = blockIdx.x;
    int widx = blk / NHd, hh = blk % NHd;
    int wi = widx % NWim;
    int wh = wi / 8, ww = wi % 8;
    int tid = threadIdx.x, lane = tid & 31, warp = tid >> 5;
    int g = lane >> 2, q = lane & 3;

    const __nv_bfloat16* base0 = qkv + (size_t)(widx * Ntok) * ThreeC + hh * HD;
    for (int idx = tid; idx < 196; idx += 128) {
        int row = idx >> 2, seg = idx & 3;
        const __nv_bfloat16* p = base0 + (size_t)row * ThreeC + seg * 8;
        uint32_t d = swz64((uint32_t)(row * 64 + seg * 16));
        *(uint4*)(smem + d)        = *(const uint4*)(p);
        *(uint4*)(smem + 4096 + d) = *(const uint4*)(p + Cc);
        *(uint4*)(smem + 8192 + d) = *(const uint4*)(p + 2 * Cc);
    }
    for (int idx = 196 + tid; idx < 256; idx += 128) {
        int row = idx >> 2, seg = idx & 3;
        uint32_t d = swz64((uint32_t)(row * 64 + seg * 16));
        uint4 z = make_uint4(0, 0, 0, 0);
        *(uint4*)(smem + d)        = z;
        *(uint4*)(smem + 4096 + d) = z;
        *(uint4*)(smem + 8192 + d) = z;
    }
    if (tid < Ntok) {
        int r = wh * WS + tid / WS, c = ww * WS + tid % WS;
        int hr = (r < Hh - WS) ? 0 : ((r < Hh - SS) ? 1 : 2);
        int wr = (c < Wd - WS) ? 0 : ((c < Wd - SS) ? 1 : 2);
        sreg[tid] = hr * 3 + wr;
    }
    for (int idx = tid; idx < 169; idx += 128)
        sbias[idx] = rpb[idx * NHd + hh];
    __syncthreads();

    float acc[8][4];
    #pragma unroll
    for (int i = 0; i < 8; i++)
        #pragma unroll
        for (int r = 0; r < 4; r++) acc[i][r] = 0.f;
    {
        uint32_t aoff = swz64((uint32_t)(warp * 16 + (lane & 15)) * 64 + (lane >> 4) * 16);
        int rowb = (lane & 7) + ((lane >> 4) << 3);
        uint32_t segb = ((lane >> 3) & 1) * 16;
        uint32_t boff[4];
        #pragma unroll
        for (int p = 0; p < 4; p++)
            boff[p] = 4096u + swz64((uint32_t)(rowb + p * 16) * 64 + segb);
        #pragma unroll
        for (int kk = 0; kk < 2; kk++) {
            uint32_t kx = (uint32_t)kk * 32;
            uint32_t a[4];
            ldsm_x4(a, sb + (aoff ^ kx));
            #pragma unroll
            for (int p = 0; p < 4; p++) {
                uint32_t b[4];
                ldsm_x4(b, sb + (boff[p] ^ kx));
                mma_bf16(acc[2 * p],     a, b[0], b[1]);
                mma_bf16(acc[2 * p + 1], a, b[2], b[3]);
            }
        }
    }

    const float scl = 0.17677669529663687f;
    int i1 = warp * 16 + g, i2 = i1 + 8;
    bool v1 = i1 < Ntok, v2 = i2 < Ntok;
    int i1d = i1 / 7, i1m = i1 - i1d * 7, r1 = v1 ? sreg[i1] : 0;
    int i2d = i2 / 7, i2m = i2 - i2d * 7, r2 = v2 ? sreg[i2] : 0;
    float mx1 = -1e30f, mx2 = -1e30f;
    #pragma unroll
    for (int ni = 0; ni < 8; ni++) {
        #pragma unroll
        for (int e = 0; e < 2; e++) {
            int j = ni * 8 + q * 2 + e;
            if (j < Ntok) {
                int jd = j / 7, jm = j - jd * 7;
                int rj = sreg[j];
                float b1v = sbias[(i1d - jd + 6) * 13 + (i1m - jm + 6)];
                float t1 = acc[ni][e] * scl + b1v + ((r1 != rj) ? -100.f : 0.f);
                acc[ni][e] = t1; mx1 = fmaxf(mx1, t1);
                float b2v = sbias[(i2d - jd + 6) * 13 + (i2m - jm + 6)];
                float t2 = acc[ni][e + 2] * scl + b2v + ((r2 != rj) ? -100.f : 0.f);
                acc[ni][e + 2] = t2; mx2 = fmaxf(mx2, t2);
            } else {
                acc[ni][e] = -1e30f; acc[ni][e + 2] = -1e30f;
            }
        }
    }
    mx1 = fmaxf(mx1, __shfl_xor_sync(0xFFFFFFFFu, mx1, 1));
    mx1 = fmaxf(mx1, __shfl_xor_sync(0xFFFFFFFFu, mx1, 2));
    mx2 = fmaxf(mx2, __shfl_xor_sync(0xFFFFFFFFu, mx2, 1));
    mx2 = fmaxf(mx2, __shfl_xor_sync(0xFFFFFFFFu, mx2, 2));
    float s1 = 0.f, s2 = 0.f;
    #pragma unroll
    for (int ni = 0; ni < 8; ni++) {
        #pragma unroll
        for (int e = 0; e < 2; e++) {
            float e1 = __expf(acc[ni][e] - mx1);     acc[ni][e] = e1;     s1 += e1;
            float e2 = __expf(acc[ni][e + 2] - mx2); acc[ni][e + 2] = e2; s2 += e2;
        }
    }
    s1 += __shfl_xor_sync(0xFFFFFFFFu, s1, 1);
    s1 += __shfl_xor_sync(0xFFFFFFFFu, s1, 2);
    s2 += __shfl_xor_sync(0xFFFFFFFFu, s2, 1);
    s2 += __shfl_xor_sync(0xFFFFFFFFu, s2, 2);
    float n1 = v1 ? (1.f / s1) : 0.f;
    float n2 = v2 ? (1.f / s2) : 0.f;

    #pragma unroll
    for (int ni = 0; ni < 8; ni++) {
        uint32_t cb = (uint32_t)(ni * 8 + q * 2) * 2;
        uint32_t o1 = 12288u + swz128((uint32_t)i1 * 128 + cb);
        uint32_t o2 = 12288u + swz128((uint32_t)i2 * 128 + cb);
        *(__nv_bfloat162*)(smem + o1) = pack_bf2(acc[ni][0] * n1, acc[ni][1] * n1);
        *(__nv_bfloat162*)(smem + o2) = pack_bf2(acc[ni][2] * n2, acc[ni][3] * n2);
    }
    __syncwarp();

    float acc2[4][4];
    #pragma unroll
    for (int i = 0; i < 4; i++)
        #pragma unroll
        for (int r = 0; r < 4; r++) acc2[i][r] = 0.f;
    {
        uint32_t a2off = 12288u + swz128((uint32_t)(warp * 16 + (lane & 15)) * 128 + (lane >> 4) * 16);
        int rv = (lane & 7) + ((lane >> 3) & 1) * 8;
        uint32_t dv8 = (uint32_t)((lane >> 4) << 3);
        uint32_t voff0 = 8192u + swz64((uint32_t)rv * 64 + dv8 * 2);
        uint32_t voff1 = 8192u + swz64((uint32_t)rv * 64 + (16 + dv8) * 2);
        #pragma unroll
        for (int ks = 0; ks < 4; ks++) {
            uint32_t a2[4], b0[4], b1[4];
            ldsm_x4(a2, sb + (a2off ^ ((uint32_t)ks * 32)));
            ldsm_x4_t(b0, sb + voff0 + (uint32_t)ks * 1024);
            ldsm_x4_t(b1, sb + voff1 + (uint32_t)ks * 1024);
            mma_bf16(acc2[0], a2, b0[0], b0[1]);
            mma_bf16(acc2[1], a2, b0[2], b0[3]);
            mma_bf16(acc2[2], a2, b1[0], b1[1]);
            mma_bf16(acc2[3], a2, b1[2], b1[3]);
        }
    }

    if (v1) {
        __nv_bfloat16* d = out + (size_t)(widx * Ntok + i1) * Cc + hh * HD + q * 2;
        #pragma unroll
        for (int dt = 0; dt < 4; dt++)
            *(__nv_bfloat162*)(d + dt * 8) = pack_bf2(acc2[dt][0], acc2[dt][1]);
    }
    if (v2) {
        __nv_bfloat16* d = out + (size_t)(widx * Ntok + i2) * Cc + hh * HD + q * 2;
        #pragma unroll
        for (int dt = 0; dt < 4; dt++)
            *(__nv_bfloat162*)(d + dt * 8) = pack_bf2(acc2[dt][2], acc2[dt][3]);
    }
}

// ---------------- host launch ----------------
extern "C" void kernel_launch(void* const* d_in, const int* in_sizes, int n_in,
                              void* d_out, int out_size) {
    const float* x      = (const float*)d_in[0];
    const float* n1w    = (const float*)d_in[1];
    const float* n1b    = (const float*)d_in[2];
    const float* qkv_w  = (const float*)d_in[3];
    const float* qkv_b  = (const float*)d_in[4];
    const float* rpb    = (const float*)d_in[5];
    const float* proj_w = (const float*)d_in[6];
    const float* proj_b = (const float*)d_in[7];
    const float* n2w    = (const float*)d_in[8];
    const float* n2b    = (const float*)d_in[9];
    const float* fc1_w  = (const float*)d_in[10];
    const float* fc1_b  = (const float*)d_in[11];
    const float* fc2_w  = (const float*)d_in[12];
    const float* fc2_b  = (const float*)d_in[13];
    float* out = (float*)d_out;

    __nv_bfloat16 *p_xw, *p_qkv, *p_attb, *p_h, *p_f1, *p_wt;
    float *p_x2w;
    cudaGetSymbolAddress((void**)&p_xw,   g_xw);
    cudaGetSymbolAddress((void**)&p_qkv,  g_qkv);
    cudaGetSymbolAddress((void**)&p_attb, g_attb);
    cudaGetSymbolAddress((void**)&p_x2w,  g_x2w);
    cudaGetSymbolAddress((void**)&p_h,    g_h);
    cudaGetSymbolAddress((void**)&p_f1,   g_f1);
    cudaGetSymbolAddress((void**)&p_wt,   g_wt);

    cudaFuncSetAttribute(k_gemm_bf<0, __nv_bfloat16>, cudaFuncAttributeMaxDynamicSharedMemorySize, SMEM_GEMM);
    cudaFuncSetAttribute(k_gemm_bf<1, __nv_bfloat16>, cudaFuncAttributeMaxDynamicSharedMemorySize, SMEM_GEMM);
    cudaFuncSetAttribute(k_gemm_bf<4, float>,         cudaFuncAttributeMaxDynamicSharedMemorySize, SMEM_GEMM);
    cudaFuncSetAttribute(k_gemm_bf<5, float>,         cudaFuncAttributeMaxDynamicSharedMemorySize, SMEM_GEMM);

    // 0. transpose + bf16 weights (single launch)
    k_transpose_all<<<1728, dim3(32, 8)>>>(qkv_w, proj_w, fc1_w, fc2_w, p_wt);

    // 1. LN1 + shift + window partition
    k_ln1<<<Mrows, 128>>>(x, n1w, n1b, p_xw);

    // 2. QKV GEMM -> bf16
    k_gemm_bf<0, __nv_bfloat16><<<dim3(ThreeC/GBN, Mrows/GBM), 256, SMEM_GEMM>>>(
        p_xw, p_wt + WT_QKV, qkv_b, nullptr, p_qkv, Mrows, ThreeC, Cc);

    // 3. tensor-core windowed attention -> bf16
    k_attn<<<(Bn * NWim) * NHd, 128>>>(p_qkv, rpb, p_attb);

    // 4. proj GEMM + gathered residual -> x2w (f32, window order)
    k_gemm_bf<4, float><<<dim3(Cc/GBN, Mrows/GBM), 256, SMEM_GEMM>>>(
        p_attb, p_wt + WT_PROJ, proj_b, x, p_x2w, Mrows, Cc, Cc);

    // 5. LN2 (window order)
    k_ln2<<<Mrows, 128>>>(p_x2w, n2w, n2b, p_h);

    // 6. fc1 GEMM + GELU -> bf16
    k_gemm_bf<1, __nv_bfloat16><<<dim3(MLPH/GBN, Mrows/GBM), 256, SMEM_GEMM>>>(
        p_h, p_wt + WT_FC1, fc1_b, nullptr, p_f1, Mrows, MLPH, Cc);

    // 7. fc2 GEMM + bias + residual, scattered to image order -> d_out
    k_gemm_bf<5, float><<<dim3(Cc/GBN, Mrows/GBM), 256, SMEM_GEMM>>>(
        p_f1, p_wt + WT_FC2, fc2_b, p_x2w, out, Mrows, Cc, MLPH);
}